// round 10
// baseline (speedup 1.0000x reference)
#include <cuda_runtime.h>
#include <cuda_fp16.h>
#include <math.h>
#include <cstdint>

#define BB 8
#define TT 512
#define DD 128
#define HH 8

typedef unsigned long long u64;

__device__ __forceinline__ u64 ffma2_(u64 a, u64 b, u64 c) {
    u64 d; asm("fma.rn.f32x2 %0, %1, %2, %3;" : "=l"(d) : "l"(a), "l"(b), "l"(c)); return d;
}
__device__ __forceinline__ float2 unpack2_(u64 v) {
    float2 f; asm("mov.b64 {%0, %1}, %2;" : "=f"(f.x), "=f"(f.y) : "l"(v)); return f;
}

// m16n8k16 f16 MMA, fp32 accumulate (portable PTX, runs on sm_103 HMMA)
__device__ __forceinline__ void mma16816_(float* c, const unsigned* a, const unsigned* b) {
    asm volatile(
        "mma.sync.aligned.m16n8k16.row.col.f32.f16.f16.f32 "
        "{%0,%1,%2,%3}, {%4,%5,%6,%7}, {%8,%9}, {%0,%1,%2,%3};"
        : "+f"(c[0]), "+f"(c[1]), "+f"(c[2]), "+f"(c[3])
        : "r"(a[0]), "r"(a[1]), "r"(a[2]), "r"(a[3]), "r"(b[0]), "r"(b[1]));
}

// |a-b| on fp16x2: HSUB2 (fma pipe) + LOP3 (alu pipe)
__device__ __forceinline__ __half2 habsdiff2_(unsigned a, unsigned b) {
    __half2 d = __hsub2(*(__half2*)&a, *(__half2*)&b);
    unsigned u = (*(unsigned*)&d) & 0x7FFF7FFFu;
    return *(__half2*)&u;
}

// Scratch
__device__ __half g_qh[(size_t)BB*HH*TT*DD];  // q[b][h][t][d] fp16
__device__ __half g_kh[(size_t)BB*HH*TT*DD];  // k[b][h][s][d] fp16 (= x*wk)
__device__ __half g_vT[(size_t)BB*HH*DD*TT];  // vT[b][h][d][s] fp16
__device__ float  g_o [BB*HH*TT*DD];          // o[b][h][t][d] fp32

// ---------------------------------------------------------------------------
// Kernel 1: QV projection via mma.sync (HMMA); q written fp16, v fp16-transposed.
// ---------------------------------------------------------------------------
#define QV_SMEM (2*64*136*2)

__global__ __launch_bounds__(256) void qv_kernel(const float* __restrict__ x,
                                                 const float* __restrict__ w) {
    extern __shared__ __half smh[];
    __half* xsh = smh;            // 64 x 136
    __half* wsh = smh + 64*136;   // 64 x 136
    __shared__ float bsh[64];

    const int tid = threadIdx.x;
    const int warp = tid >> 5, lane = tid & 31;
    const int g = lane >> 2, tg = lane & 3;
    const int mt = warp & 3, ng = warp >> 2;
    const int m0 = blockIdx.y * 64;
    const int n0 = blockIdx.x * 64;

    const float4* xg = (const float4*)(x + (size_t)m0*DD);
    for (int i = tid; i < 64*32; i += 256) {
        int r = i >> 5, c4 = i & 31;
        float4 v = xg[i];
        __half2 h0 = __floats2half2_rn(v.x, v.y);
        __half2 h1 = __floats2half2_rn(v.z, v.w);
        uint2 st; st.x = *(unsigned*)&h0; st.y = *(unsigned*)&h1;
        *(uint2*)&xsh[r*136 + c4*4] = st;
    }
    for (int i = tid; i < 64*64; i += 256) {
        int r = i >> 6, c2 = i & 63;
        const float* wr = w + (size_t)(n0 + r)*129 + c2*2;
        __half2 h = __floats2half2_rn(wr[0], wr[1]);
        *(unsigned*)&wsh[r*136 + c2*2] = *(unsigned*)&h;
    }
    if (tid < 64) bsh[tid] = w[(size_t)(n0 + tid)*129 + 128];
    __syncthreads();

    float oacc[4][4];
#pragma unroll
    for (int nt = 0; nt < 4; nt++)
#pragma unroll
        for (int c = 0; c < 4; c++) oacc[nt][c] = 0.f;

#pragma unroll
    for (int kk = 0; kk < 8; kk++) {
        unsigned af[4];
        const int ar = (mt*16 + g)*136 + kk*16 + tg*2;
        af[0] = *(const unsigned*)&xsh[ar];
        af[1] = *(const unsigned*)&xsh[ar + 8*136];
        af[2] = *(const unsigned*)&xsh[ar + 8];
        af[3] = *(const unsigned*)&xsh[ar + 8*136 + 8];
#pragma unroll
        for (int nt = 0; nt < 4; nt++) {
            const int br = (ng*32 + nt*8 + g)*136 + kk*16 + tg*2;
            unsigned bf[2];
            bf[0] = *(const unsigned*)&wsh[br];
            bf[1] = *(const unsigned*)&wsh[br + 8];
            mma16816_(oacc[nt], af, bf);
        }
    }

#pragma unroll
    for (int nt = 0; nt < 4; nt++) {
        const int col = ng*32 + nt*8 + tg*2;
        oacc[nt][0] += bsh[col];     oacc[nt][1] += bsh[col + 1];
        oacc[nt][2] += bsh[col];     oacc[nt][3] += bsh[col + 1];
    }

    const int bi = m0 >> 9, tb = m0 & 511;
    const int cbase = n0 & 255;
    const int hh = n0 >> 8;

    if (cbase < 128) {
        // q tile: fp16 stores
        __half* qg_ = g_qh + ((size_t)(bi*HH + hh)*TT + tb)*DD + cbase;
#pragma unroll
        for (int nt = 0; nt < 4; nt++) {
            const int col = ng*32 + nt*8 + tg*2;
            const int r0 = mt*16 + g;
            __half2 h01 = __floats2half2_rn(oacc[nt][0], oacc[nt][1]);
            __half2 h23 = __floats2half2_rn(oacc[nt][2], oacc[nt][3]);
            *(unsigned*)&qg_[(size_t)r0*DD + col]       = *(unsigned*)&h01;
            *(unsigned*)&qg_[(size_t)(r0 + 8)*DD + col] = *(unsigned*)&h23;
        }
    } else {
        // v tile: transpose through smem, coalesced fp16 stores to g_vT
        __syncthreads();
        __half* vsm = xsh;             // 64 d-rows x 72 (t stride)
#pragma unroll
        for (int nt = 0; nt < 4; nt++) {
            const int dl = ng*32 + nt*8 + tg*2;
            const int r0 = mt*16 + g;
            vsm[dl*72 + r0]           = __float2half(oacc[nt][0]);
            vsm[(dl + 1)*72 + r0]     = __float2half(oacc[nt][1]);
            vsm[dl*72 + r0 + 8]       = __float2half(oacc[nt][2]);
            vsm[(dl + 1)*72 + r0 + 8] = __float2half(oacc[nt][3]);
        }
        __syncthreads();
        __half* vg = g_vT + ((size_t)(bi*HH + hh)*DD + (cbase - 128))*TT + tb;
        for (int i = tid; i < 1024; i += 256) {
            int row = i >> 4, seg = i & 15;
            uint2 val = *(uint2*)&vsm[row*72 + seg*4];
            *(uint2*)&vg[(size_t)row*TT + seg*4] = val;
        }
    }
}

// ---------------------------------------------------------------------------
// Kernel 1b: k[b][h][s][d] = x[b][s][d] * wk[h][d], fp16. Tiny (~5us).
// Block: (b, 16 s-rows). 256 threads.
// ---------------------------------------------------------------------------
__global__ __launch_bounds__(256) void k_kernel(const float* __restrict__ x,
                                                const float* __restrict__ wk) {
    __shared__ float xs[16*128];
    __shared__ float wks[8*128];

    const int b = blockIdx.y, s0 = blockIdx.x * 16;
    const int tid = threadIdx.x;

    const float4* xg = (const float4*)(x + ((size_t)b*TT + s0)*DD);
    for (int i = tid; i < 16*32; i += 256) ((float4*)xs)[i] = xg[i];
    for (int i = tid; i < 8*32; i += 256)  ((float4*)wks)[i] = ((const float4*)wk)[i];
    __syncthreads();

    for (int i = tid; i < 16*8*64; i += 256) {
        int d2 = i & 63, hh = (i >> 6) & 7, sl = i >> 9;
        float2 xv = *(const float2*)&xs[sl*128 + d2*2];
        float2 wv = *(const float2*)&wks[hh*128 + d2*2];
        __half2 h = __floats2half2_rn(xv.x*wv.x, xv.y*wv.y);
        *(unsigned*)&g_kh[((size_t)(b*HH + hh)*TT + s0 + sl)*DD + d2*2] = *(unsigned*)&h;
    }
}

// ---------------------------------------------------------------------------
// Kernel 2: fused L1 attention. fp16 absdiff distance (flush every 64 d),
// double-buffered k tiles, HMMA P@V.
// smem (bytes):
//   [0,133120)        Ssh f32 64 x 520
//   [133120,150528)   qsh fp16 64x136     | phase3 vTsh fp16 128x136 overlays
//   [150528,167936)   ksh0 fp16 64x136    |   [133120,167936)
//   [167936,185344)   ksh1 fp16 64x136
// ---------------------------------------------------------------------------
#define SSTRIDE 520
#define OFF_QH 133120
#define OFF_K0 150528
#define OFF_K1 167936
#define OFF_VT 133120
#define ATTN_SMEM 185344

__global__ __launch_bounds__(256) void attn_kernel(const float* __restrict__ msk) {
    extern __shared__ char smc[];
    float*  Ssh = (float*)smc;
    __half* qsh = (__half*)(smc + OFF_QH);
    __half* kbuf[2] = { (__half*)(smc + OFF_K0), (__half*)(smc + OFF_K1) };

    const int b  = blockIdx.z, h = blockIdx.y;
    const int t0 = blockIdx.x * 64;
    const int tid = threadIdx.x;
    const int tx  = tid & 15, ty = tid >> 4;

    const __half* khg = g_kh + ((size_t)(b*HH + h))*TT*DD;

    // stage q tile (fp16 copy)
    const uint4* qg = (const uint4*)(g_qh + (((size_t)(b*HH + h))*TT + t0)*DD);
#pragma unroll
    for (int u = 0; u < 4; u++) {
        int i = tid + u*256;
        int r = i >> 4, kg = i & 15;
        *(uint4*)&qsh[r*136 + kg*8] = qg[i];
    }
    // stage k tile 0
    {
        const uint4* kg_ = (const uint4*)khg;
#pragma unroll
        for (int u = 0; u < 4; u++) {
            int i = tid + u*256;
            int r = i >> 4, kg = i & 15;
            *(uint4*)&kbuf[0][r*136 + kg*8] = kg_[i];
        }
    }
    __syncthreads();

    const float NEG_ISQ = -0.08838834764831845f;  // -1/sqrt(128)

    // ---------------- Phase 1: score tiles ----------------
    for (int sc = 0; sc < 8; sc++) {
        // stage next tile into the other buffer (overlaps with compute below)
        if (sc + 1 < 8) {
            const uint4* kg_ = (const uint4*)(khg + (size_t)(sc + 1)*64*DD);
            __half* dst = kbuf[(sc + 1) & 1];
#pragma unroll
            for (int u = 0; u < 4; u++) {
                int i = tid + u*256;
                int r = i >> 4, kg = i & 15;
                *(uint4*)&dst[r*136 + kg*8] = kg_[i];
            }
        }
        const __half* ksh = kbuf[sc & 1];
        const int s0 = sc * 64;

        float facc[4][4];
#pragma unroll
        for (int i = 0; i < 4; i++)
#pragma unroll
            for (int j = 0; j < 4; j++) facc[i][j] = 0.f;

#pragma unroll
        for (int hf = 0; hf < 2; hf++) {
            __half2 hacc[4][4];
            const __half2 hz = __float2half2_rn(0.f);
#pragma unroll
            for (int i = 0; i < 4; i++)
#pragma unroll
                for (int j = 0; j < 4; j++) hacc[i][j] = hz;

#pragma unroll
            for (int dp = 0; dp < 64; dp += 8) {
                const int d = hf*64 + dp;
                uint4 qv[4], kv[4];
#pragma unroll
                for (int i = 0; i < 4; i++) qv[i] = *(const uint4*)&qsh[(ty*4 + i)*136 + d];
#pragma unroll
                for (int j = 0; j < 4; j++) kv[j] = *(const uint4*)&ksh[(tx + 16*j)*136 + d];
#pragma unroll
                for (int i = 0; i < 4; i++)
#pragma unroll
                    for (int j = 0; j < 4; j++) {
                        __half2 a = hacc[i][j];
                        a = __hadd2(a, habsdiff2_(qv[i].x, kv[j].x));
                        a = __hadd2(a, habsdiff2_(qv[i].y, kv[j].y));
                        a = __hadd2(a, habsdiff2_(qv[i].z, kv[j].z));
                        a = __hadd2(a, habsdiff2_(qv[i].w, kv[j].w));
                        hacc[i][j] = a;
                    }
            }
#pragma unroll
            for (int i = 0; i < 4; i++)
#pragma unroll
                for (int j = 0; j < 4; j++) {
                    float2 f = __half22float2(hacc[i][j]);
                    facc[i][j] += f.x;
                    facc[i][j] += f.y;
                }
        }

#pragma unroll
        for (int i = 0; i < 4; i++)
#pragma unroll
            for (int j = 0; j < 4; j++)
                Ssh[(ty*4 + i)*SSTRIDE + s0 + tx + 16*j] = facc[i][j] * NEG_ISQ;
        __syncthreads();
    }

    // ---------------- Phase 2: row softmax + mask ----------------
    const int warp = tid >> 5, lane = tid & 31;
    for (int r = warp; r < 64; r += 8) {
        float* row = Ssh + r*SSTRIDE;
        float vals[16];
        float m = -1e30f;
#pragma unroll
        for (int i = 0; i < 16; i++) { vals[i] = row[lane + i*32]; m = fmaxf(m, vals[i]); }
#pragma unroll
        for (int o = 16; o > 0; o >>= 1) m = fmaxf(m, __shfl_xor_sync(0xffffffffu, m, o));
        float sum = 0.f;
#pragma unroll
        for (int i = 0; i < 16; i++) { vals[i] = __expf(vals[i] - m); sum += vals[i]; }
#pragma unroll
        for (int o = 16; o > 0; o >>= 1) sum += __shfl_xor_sync(0xffffffffu, sum, o);
        float inv = 1.f / sum;
        const float* mrow = msk + ((size_t)(h*TT + t0 + r))*TT;
#pragma unroll
        for (int i = 0; i < 16; i++)
            row[lane + i*32] = vals[i] * inv * mrow[lane + i*32];
    }
    __syncthreads();

    // ---------------- Phase 3: O = P @ V via mma.sync ----------------
    __half* vTsh = (__half*)(smc + OFF_VT);
    const __half* vTg = g_vT + ((size_t)(b*HH + h))*DD*TT;
    const int mt = warp & 3, ng = warp >> 2;
    const int g = lane >> 2, tg = lane & 3;

    float oacc[8][4];
#pragma unroll
    for (int nt = 0; nt < 8; nt++)
#pragma unroll
        for (int c = 0; c < 4; c++) oacc[nt][c] = 0.f;

    for (int sc = 0; sc < 4; sc++) {
        const int s0 = sc * 128;
        for (int i = tid; i < 2048; i += 256) {
            int r = i >> 4, kg = i & 15;
            uint4 val = *(const uint4*)(vTg + (size_t)r*TT + s0 + kg*8);
            *(uint4*)&vTsh[r*136 + kg*8] = val;
        }
        __syncthreads();

#pragma unroll
        for (int kk = 0; kk < 8; kk++) {
            const int ar = (mt*16 + g)*SSTRIDE + s0 + kk*16 + tg*2;
            float2 a01 = *(const float2*)&Ssh[ar];
            float2 a23 = *(const float2*)&Ssh[ar + 8*SSTRIDE];
            float2 a45 = *(const float2*)&Ssh[ar + 8];
            float2 a67 = *(const float2*)&Ssh[ar + 8*SSTRIDE + 8];
            unsigned af[4];
            __half2 h0 = __floats2half2_rn(a01.x, a01.y); af[0] = *(unsigned*)&h0;
            __half2 h1 = __floats2half2_rn(a23.x, a23.y); af[1] = *(unsigned*)&h1;
            __half2 h2 = __floats2half2_rn(a45.x, a45.y); af[2] = *(unsigned*)&h2;
            __half2 h3 = __floats2half2_rn(a67.x, a67.y); af[3] = *(unsigned*)&h3;

            const int kb = kk*16 + tg*2;
#pragma unroll
            for (int nt = 0; nt < 8; nt++) {
                int row = ng*64 + nt*8 + g;
                unsigned bf[2];
                bf[0] = *(const unsigned*)&vTsh[row*136 + kb];
                bf[1] = *(const unsigned*)&vTsh[row*136 + kb + 8];
                mma16816_(oacc[nt], af, bf);
            }
        }
        __syncthreads();
    }

    float* og = g_o + (((size_t)(b*HH + h))*TT + t0)*DD;
#pragma unroll
    for (int nt = 0; nt < 8; nt++) {
        int d = ng*64 + nt*8 + tg*2;
        int r0 = mt*16 + g;
        *(float2*)&og[(size_t)r0*DD + d]       = make_float2(oacc[nt][0], oacc[nt][1]);
        *(float2*)&og[(size_t)(r0 + 8)*DD + d] = make_float2(oacc[nt][2], oacc[nt][3]);
    }
}

// ---------------------------------------------------------------------------
// Kernel 3: head-reduce + quickGELU + fanout + residual (unchanged)
// ---------------------------------------------------------------------------
__global__ __launch_bounds__(256) void final_kernel(const float* __restrict__ x,
                                                    const float* __restrict__ fw,
                                                    float* __restrict__ out) {
    extern __shared__ float sm[];
    float* Wsh  = sm;            // 128*130
    float* yosh = sm + 128*130;  // 16*128

    const int b = blockIdx.y, t0 = blockIdx.x * 16;
    const int tid = threadIdx.x;

    for (int i = tid; i < 128*129; i += 256) {
        int r = i / 129, c = i - r*129;
        Wsh[r*130 + c] = fw[i];
    }

    for (int i = tid; i < 16*128; i += 256) {
        int r = i >> 7, dd = i & 127;
        float bo = 0.f;
#pragma unroll
        for (int h = 0; h < HH; h++)
            bo += g_o[(((size_t)(b*HH + h))*TT + t0 + r)*DD + dd];
        float z  = bo + 4.5f;
        float sg = 1.f / (1.f + __expf(-1.702f * z));
        yosh[r*128 + dd] = z*sg - 4.5f;
    }
    __syncthreads();

    const int o = tid & 127, half = tid >> 7;
    u64 acc2[8];
#pragma unroll
    for (int rr = 0; rr < 8; rr++) acc2[rr] = 0ULL;

#pragma unroll 4
    for (int i = 0; i < 128; i += 2) {
        u64 w2 = *(const u64*)&Wsh[o*130 + i];
#pragma unroll
        for (int rr = 0; rr < 8; rr++)
            acc2[rr] = ffma2_(w2, *(const u64*)&yosh[(half*8 + rr)*128 + i], acc2[rr]);
    }
    float bias = Wsh[o*130 + 128];
#pragma unroll
    for (int rr = 0; rr < 8; rr++) {
        int t = t0 + half*8 + rr;
        size_t idx = ((size_t)b*TT + t)*DD + o;
        float2 f = unpack2_(acc2[rr]);
        out[idx] = x[idx] + f.x + f.y + bias;
    }
}

// ---------------------------------------------------------------------------
extern "C" void kernel_launch(void* const* d_in, const int* in_sizes, int n_in,
                              void* d_out, int out_size) {
    const float* x   = (const float*)d_in[0];
    const float* msk = (const float*)d_in[1];
    const float* wqv = (const float*)d_in[2];
    const float* wk  = (const float*)d_in[3];
    const float* fw  = (const float*)d_in[4];
    float* out = (float*)d_out;

    cudaFuncSetAttribute(qv_kernel,    cudaFuncAttributeMaxDynamicSharedMemorySize,
                         QV_SMEM);
    cudaFuncSetAttribute(attn_kernel,  cudaFuncAttributeMaxDynamicSharedMemorySize,
                         ATTN_SMEM);
    cudaFuncSetAttribute(final_kernel, cudaFuncAttributeMaxDynamicSharedMemorySize,
                         (128*130 + 16*128) * 4);

    qv_kernel<<<dim3(32, 64), 256, QV_SMEM>>>(x, wqv);
    k_kernel<<<dim3(TT/16, BB), 256>>>(x, wk);
    attn_kernel<<<dim3(TT/64, HH, BB), 256, ATTN_SMEM>>>(msk);
    final_kernel<<<dim3(TT/16, BB), 256, (128*130 + 16*128) * 4>>>(x, fw, out);
}

// round 11
// speedup vs baseline: 1.1087x; 1.1087x over previous
#include <cuda_runtime.h>
#include <cuda_fp16.h>
#include <math.h>
#include <cstdint>

#define BB 8
#define TT 512
#define DD 128
#define HH 8

typedef unsigned long long u64;

__device__ __forceinline__ u64 ffma2_(u64 a, u64 b, u64 c) {
    u64 d; asm("fma.rn.f32x2 %0, %1, %2, %3;" : "=l"(d) : "l"(a), "l"(b), "l"(c)); return d;
}
__device__ __forceinline__ float2 unpack2_(u64 v) {
    float2 f; asm("mov.b64 {%0, %1}, %2;" : "=f"(f.x), "=f"(f.y) : "l"(v)); return f;
}

// m16n8k16 f16 MMA, fp32 accumulate (portable PTX, runs on sm_103 HMMA)
__device__ __forceinline__ void mma16816_(float* c, const unsigned* a, const unsigned* b) {
    asm volatile(
        "mma.sync.aligned.m16n8k16.row.col.f32.f16.f16.f32 "
        "{%0,%1,%2,%3}, {%4,%5,%6,%7}, {%8,%9}, {%0,%1,%2,%3};"
        : "+f"(c[0]), "+f"(c[1]), "+f"(c[2]), "+f"(c[3])
        : "r"(a[0]), "r"(a[1]), "r"(a[2]), "r"(a[3]), "r"(b[0]), "r"(b[1]));
}

// |a-b| on fp16x2: HSUB2 (fma pipe) + LOP3 (alu pipe)
__device__ __forceinline__ __half2 habsdiff2_(unsigned a, unsigned b) {
    __half2 d = __hsub2(*(__half2*)&a, *(__half2*)&b);
    unsigned u = (*(unsigned*)&d) & 0x7FFF7FFFu;
    return *(__half2*)&u;
}

// Scratch
__device__ __half g_qh[(size_t)BB*HH*TT*DD];  // q[b][h][t][d] fp16
__device__ __half g_kh[(size_t)BB*HH*TT*DD];  // k[b][h][s][d] fp16 (= x*wk)
__device__ __half g_vT[(size_t)BB*HH*DD*TT];  // vT[b][h][d][s] fp16
__device__ float  g_o [BB*HH*TT*DD];          // o[b][h][t][d] fp32

// ---------------------------------------------------------------------------
// Kernel 1: QV projection via mma.sync (HMMA); q written fp16, v fp16-transposed.
// ---------------------------------------------------------------------------
#define QV_SMEM (2*64*136*2)

__global__ __launch_bounds__(256) void qv_kernel(const float* __restrict__ x,
                                                 const float* __restrict__ w) {
    extern __shared__ __half smh[];
    __half* xsh = smh;            // 64 x 136
    __half* wsh = smh + 64*136;   // 64 x 136
    __shared__ float bsh[64];

    const int tid = threadIdx.x;
    const int warp = tid >> 5, lane = tid & 31;
    const int g = lane >> 2, tg = lane & 3;
    const int mt = warp & 3, ng = warp >> 2;
    const int m0 = blockIdx.y * 64;
    const int n0 = blockIdx.x * 64;

    const float4* xg = (const float4*)(x + (size_t)m0*DD);
    for (int i = tid; i < 64*32; i += 256) {
        int r = i >> 5, c4 = i & 31;
        float4 v = xg[i];
        __half2 h0 = __floats2half2_rn(v.x, v.y);
        __half2 h1 = __floats2half2_rn(v.z, v.w);
        uint2 st; st.x = *(unsigned*)&h0; st.y = *(unsigned*)&h1;
        *(uint2*)&xsh[r*136 + c4*4] = st;
    }
    for (int i = tid; i < 64*64; i += 256) {
        int r = i >> 6, c2 = i & 63;
        const float* wr = w + (size_t)(n0 + r)*129 + c2*2;
        __half2 h = __floats2half2_rn(wr[0], wr[1]);
        *(unsigned*)&wsh[r*136 + c2*2] = *(unsigned*)&h;
    }
    if (tid < 64) bsh[tid] = w[(size_t)(n0 + tid)*129 + 128];
    __syncthreads();

    float oacc[4][4];
#pragma unroll
    for (int nt = 0; nt < 4; nt++)
#pragma unroll
        for (int c = 0; c < 4; c++) oacc[nt][c] = 0.f;

#pragma unroll
    for (int kk = 0; kk < 8; kk++) {
        unsigned af[4];
        const int ar = (mt*16 + g)*136 + kk*16 + tg*2;
        af[0] = *(const unsigned*)&xsh[ar];
        af[1] = *(const unsigned*)&xsh[ar + 8*136];
        af[2] = *(const unsigned*)&xsh[ar + 8];
        af[3] = *(const unsigned*)&xsh[ar + 8*136 + 8];
#pragma unroll
        for (int nt = 0; nt < 4; nt++) {
            const int br = (ng*32 + nt*8 + g)*136 + kk*16 + tg*2;
            unsigned bf[2];
            bf[0] = *(const unsigned*)&wsh[br];
            bf[1] = *(const unsigned*)&wsh[br + 8];
            mma16816_(oacc[nt], af, bf);
        }
    }

#pragma unroll
    for (int nt = 0; nt < 4; nt++) {
        const int col = ng*32 + nt*8 + tg*2;
        oacc[nt][0] += bsh[col];     oacc[nt][1] += bsh[col + 1];
        oacc[nt][2] += bsh[col];     oacc[nt][3] += bsh[col + 1];
    }

    const int bi = m0 >> 9, tb = m0 & 511;
    const int cbase = n0 & 255;
    const int hh = n0 >> 8;

    if (cbase < 128) {
        __half* qg_ = g_qh + ((size_t)(bi*HH + hh)*TT + tb)*DD + cbase;
#pragma unroll
        for (int nt = 0; nt < 4; nt++) {
            const int col = ng*32 + nt*8 + tg*2;
            const int r0 = mt*16 + g;
            __half2 h01 = __floats2half2_rn(oacc[nt][0], oacc[nt][1]);
            __half2 h23 = __floats2half2_rn(oacc[nt][2], oacc[nt][3]);
            *(unsigned*)&qg_[(size_t)r0*DD + col]       = *(unsigned*)&h01;
            *(unsigned*)&qg_[(size_t)(r0 + 8)*DD + col] = *(unsigned*)&h23;
        }
    } else {
        __syncthreads();
        __half* vsm = xsh;             // 64 d-rows x 72 (t stride)
#pragma unroll
        for (int nt = 0; nt < 4; nt++) {
            const int dl = ng*32 + nt*8 + tg*2;
            const int r0 = mt*16 + g;
            vsm[dl*72 + r0]           = __float2half(oacc[nt][0]);
            vsm[(dl + 1)*72 + r0]     = __float2half(oacc[nt][1]);
            vsm[dl*72 + r0 + 8]       = __float2half(oacc[nt][2]);
            vsm[(dl + 1)*72 + r0 + 8] = __float2half(oacc[nt][3]);
        }
        __syncthreads();
        __half* vg = g_vT + ((size_t)(bi*HH + hh)*DD + (cbase - 128))*TT + tb;
        for (int i = tid; i < 1024; i += 256) {
            int row = i >> 4, seg = i & 15;
            uint2 val = *(uint2*)&vsm[row*72 + seg*4];
            *(uint2*)&vg[(size_t)row*TT + seg*4] = val;
        }
    }
}

// ---------------------------------------------------------------------------
// Kernel 1b: k[b][h][s][d] = x[b][s][d] * wk[h][d], fp16. Tiny (~5us).
// ---------------------------------------------------------------------------
__global__ __launch_bounds__(256) void k_kernel(const float* __restrict__ x,
                                                const float* __restrict__ wk) {
    __shared__ float xs[16*128];
    __shared__ float wks[8*128];

    const int b = blockIdx.y, s0 = blockIdx.x * 16;
    const int tid = threadIdx.x;

    const float4* xg = (const float4*)(x + ((size_t)b*TT + s0)*DD);
    for (int i = tid; i < 16*32; i += 256) ((float4*)xs)[i] = xg[i];
    for (int i = tid; i < 8*32; i += 256)  ((float4*)wks)[i] = ((const float4*)wk)[i];
    __syncthreads();

    for (int i = tid; i < 16*8*64; i += 256) {
        int d2 = i & 63, hh = (i >> 6) & 7, sl = i >> 9;
        float2 xv = *(const float2*)&xs[sl*128 + d2*2];
        float2 wv = *(const float2*)&wks[hh*128 + d2*2];
        __half2 h = __floats2half2_rn(xv.x*wv.x, xv.y*wv.y);
        *(unsigned*)&g_kh[((size_t)(b*HH + hh)*TT + s0 + sl)*DD + d2*2] = *(unsigned*)&h;
    }
}

// ---------------------------------------------------------------------------
// Kernel 2: fused L1 attention. fp16 absdiff distance (flush every 64 d),
// register-prefetch k staging (R9 pipeline), HMMA P@V.
// smem (bytes):
//   [0,133120)        Ssh f32 64 x 520
//   [133120,150528)   qsh fp16 64x136     | phase3 vTsh fp16 128x136 overlays
//   [150528,167936)   ksh fp16 64x136     |   [133120,167936)
// ---------------------------------------------------------------------------
#define SSTRIDE 520
#define OFF_QH 133120
#define OFF_KH 150528
#define OFF_VT 133120
#define ATTN_SMEM 167936

__global__ __launch_bounds__(256) void attn_kernel(const float* __restrict__ msk) {
    extern __shared__ char smc[];
    float*  Ssh = (float*)smc;
    __half* qsh = (__half*)(smc + OFF_QH);
    __half* ksh = (__half*)(smc + OFF_KH);

    const int b  = blockIdx.z, h = blockIdx.y;
    const int t0 = blockIdx.x * 64;
    const int tid = threadIdx.x;
    const int tx  = tid & 15, ty = tid >> 4;

    const uint4* khg = (const uint4*)(g_kh + ((size_t)(b*HH + h))*TT*DD);

    // stage q tile (fp16 copy)
    const uint4* qg = (const uint4*)(g_qh + (((size_t)(b*HH + h))*TT + t0)*DD);
#pragma unroll
    for (int u = 0; u < 4; u++) {
        int i = tid + u*256;
        int r = i >> 4, kg = i & 15;
        *(uint4*)&qsh[r*136 + kg*8] = qg[i];
    }

    const float NEG_ISQ = -0.08838834764831845f;  // -1/sqrt(128)

    // prefetch k tile 0 into registers
    uint4 kreg[4];
#pragma unroll
    for (int u = 0; u < 4; u++) kreg[u] = khg[tid + u*256];

    // ---------------- Phase 1: score tiles ----------------
    for (int sc = 0; sc < 8; sc++) {
        const int s0 = sc * 64;
        // store prefetched tile
#pragma unroll
        for (int u = 0; u < 4; u++) {
            int i = tid + u*256;
            int r = i >> 4, kg = i & 15;
            *(uint4*)&ksh[r*136 + kg*8] = kreg[u];
        }
        __syncthreads();

        // issue next tile's loads (hidden behind the compute below)
        if (sc + 1 < 8) {
#pragma unroll
            for (int u = 0; u < 4; u++) kreg[u] = khg[(sc + 1)*1024 + tid + u*256];
        }

        float facc[4][4];
#pragma unroll
        for (int i = 0; i < 4; i++)
#pragma unroll
            for (int j = 0; j < 4; j++) facc[i][j] = 0.f;

#pragma unroll
        for (int hf = 0; hf < 2; hf++) {
            __half2 hacc[4][4];
            const __half2 hz = __float2half2_rn(0.f);
#pragma unroll
            for (int i = 0; i < 4; i++)
#pragma unroll
                for (int j = 0; j < 4; j++) hacc[i][j] = hz;

#pragma unroll
            for (int dp = 0; dp < 64; dp += 8) {
                const int d = hf*64 + dp;
                uint4 qv[4], kv[4];
#pragma unroll
                for (int i = 0; i < 4; i++) qv[i] = *(const uint4*)&qsh[(ty*4 + i)*136 + d];
#pragma unroll
                for (int j = 0; j < 4; j++) kv[j] = *(const uint4*)&ksh[(tx + 16*j)*136 + d];
#pragma unroll
                for (int i = 0; i < 4; i++)
#pragma unroll
                    for (int j = 0; j < 4; j++) {
                        __half2 a = hacc[i][j];
                        a = __hadd2(a, habsdiff2_(qv[i].x, kv[j].x));
                        a = __hadd2(a, habsdiff2_(qv[i].y, kv[j].y));
                        a = __hadd2(a, habsdiff2_(qv[i].z, kv[j].z));
                        a = __hadd2(a, habsdiff2_(qv[i].w, kv[j].w));
                        hacc[i][j] = a;
                    }
            }
#pragma unroll
            for (int i = 0; i < 4; i++)
#pragma unroll
                for (int j = 0; j < 4; j++) {
                    float2 f = __half22float2(hacc[i][j]);
                    facc[i][j] += f.x;
                    facc[i][j] += f.y;
                }
        }

#pragma unroll
        for (int i = 0; i < 4; i++)
#pragma unroll
            for (int j = 0; j < 4; j++)
                Ssh[(ty*4 + i)*SSTRIDE + s0 + tx + 16*j] = facc[i][j] * NEG_ISQ;
        __syncthreads();
    }

    // ---------------- Phase 2: row softmax + mask ----------------
    const int warp = tid >> 5, lane = tid & 31;
    for (int r = warp; r < 64; r += 8) {
        float* row = Ssh + r*SSTRIDE;
        float vals[16];
        float m = -1e30f;
#pragma unroll
        for (int i = 0; i < 16; i++) { vals[i] = row[lane + i*32]; m = fmaxf(m, vals[i]); }
#pragma unroll
        for (int o = 16; o > 0; o >>= 1) m = fmaxf(m, __shfl_xor_sync(0xffffffffu, m, o));
        float sum = 0.f;
#pragma unroll
        for (int i = 0; i < 16; i++) { vals[i] = __expf(vals[i] - m); sum += vals[i]; }
#pragma unroll
        for (int o = 16; o > 0; o >>= 1) sum += __shfl_xor_sync(0xffffffffu, sum, o);
        float inv = 1.f / sum;
        const float* mrow = msk + ((size_t)(h*TT + t0 + r))*TT;
#pragma unroll
        for (int i = 0; i < 16; i++)
            row[lane + i*32] = vals[i] * inv * mrow[lane + i*32];
    }
    __syncthreads();

    // ---------------- Phase 3: O = P @ V via mma.sync ----------------
    __half* vTsh = (__half*)(smc + OFF_VT);
    const __half* vTg = g_vT + ((size_t)(b*HH + h))*DD*TT;
    const int mt = warp & 3, ng = warp >> 2;
    const int g = lane >> 2, tg = lane & 3;

    float oacc[8][4];
#pragma unroll
    for (int nt = 0; nt < 8; nt++)
#pragma unroll
        for (int c = 0; c < 4; c++) oacc[nt][c] = 0.f;

    for (int sc = 0; sc < 4; sc++) {
        const int s0 = sc * 128;
        for (int i = tid; i < 2048; i += 256) {
            int r = i >> 4, kg = i & 15;
            uint4 val = *(const uint4*)(vTg + (size_t)r*TT + s0 + kg*8);
            *(uint4*)&vTsh[r*136 + kg*8] = val;
        }
        __syncthreads();

#pragma unroll
        for (int kk = 0; kk < 8; kk++) {
            const int ar = (mt*16 + g)*SSTRIDE + s0 + kk*16 + tg*2;
            float2 a01 = *(const float2*)&Ssh[ar];
            float2 a23 = *(const float2*)&Ssh[ar + 8*SSTRIDE];
            float2 a45 = *(const float2*)&Ssh[ar + 8];
            float2 a67 = *(const float2*)&Ssh[ar + 8*SSTRIDE + 8];
            unsigned af[4];
            __half2 h0 = __floats2half2_rn(a01.x, a01.y); af[0] = *(unsigned*)&h0;
            __half2 h1 = __floats2half2_rn(a23.x, a23.y); af[1] = *(unsigned*)&h1;
            __half2 h2 = __floats2half2_rn(a45.x, a45.y); af[2] = *(unsigned*)&h2;
            __half2 h3 = __floats2half2_rn(a67.x, a67.y); af[3] = *(unsigned*)&h3;

            const int kb = kk*16 + tg*2;
#pragma unroll
            for (int nt = 0; nt < 8; nt++) {
                int row = ng*64 + nt*8 + g;
                unsigned bf[2];
                bf[0] = *(const unsigned*)&vTsh[row*136 + kb];
                bf[1] = *(const unsigned*)&vTsh[row*136 + kb + 8];
                mma16816_(oacc[nt], af, bf);
            }
        }
        __syncthreads();
    }

    float* og = g_o + (((size_t)(b*HH + h))*TT + t0)*DD;
#pragma unroll
    for (int nt = 0; nt < 8; nt++) {
        int d = ng*64 + nt*8 + tg*2;
        int r0 = mt*16 + g;
        *(float2*)&og[(size_t)r0*DD + d]       = make_float2(oacc[nt][0], oacc[nt][1]);
        *(float2*)&og[(size_t)(r0 + 8)*DD + d] = make_float2(oacc[nt][2], oacc[nt][3]);
    }
}

// ---------------------------------------------------------------------------
// Kernel 3: head-reduce + quickGELU + fanout + residual (unchanged)
// ---------------------------------------------------------------------------
__global__ __launch_bounds__(256) void final_kernel(const float* __restrict__ x,
                                                    const float* __restrict__ fw,
                                                    float* __restrict__ out) {
    extern __shared__ float sm[];
    float* Wsh  = sm;            // 128*130
    float* yosh = sm + 128*130;  // 16*128

    const int b = blockIdx.y, t0 = blockIdx.x * 16;
    const int tid = threadIdx.x;

    for (int i = tid; i < 128*129; i += 256) {
        int r = i / 129, c = i - r*129;
        Wsh[r*130 + c] = fw[i];
    }

    for (int i = tid; i < 16*128; i += 256) {
        int r = i >> 7, dd = i & 127;
        float bo = 0.f;
#pragma unroll
        for (int h = 0; h < HH; h++)
            bo += g_o[(((size_t)(b*HH + h))*TT + t0 + r)*DD + dd];
        float z  = bo + 4.5f;
        float sg = 1.f / (1.f + __expf(-1.702f * z));
        yosh[r*128 + dd] = z*sg - 4.5f;
    }
    __syncthreads();

    const int o = tid & 127, half = tid >> 7;
    u64 acc2[8];
#pragma unroll
    for (int rr = 0; rr < 8; rr++) acc2[rr] = 0ULL;

#pragma unroll 4
    for (int i = 0; i < 128; i += 2) {
        u64 w2 = *(const u64*)&Wsh[o*130 + i];
#pragma unroll
        for (int rr = 0; rr < 8; rr++)
            acc2[rr] = ffma2_(w2, *(const u64*)&yosh[(half*8 + rr)*128 + i], acc2[rr]);
    }
    float bias = Wsh[o*130 + 128];
#pragma unroll
    for (int rr = 0; rr < 8; rr++) {
        int t = t0 + half*8 + rr;
        size_t idx = ((size_t)b*TT + t)*DD + o;
        float2 f = unpack2_(acc2[rr]);
        out[idx] = x[idx] + f.x + f.y + bias;
    }
}

// ---------------------------------------------------------------------------
extern "C" void kernel_launch(void* const* d_in, const int* in_sizes, int n_in,
                              void* d_out, int out_size) {
    const float* x   = (const float*)d_in[0];
    const float* msk = (const float*)d_in[1];
    const float* wqv = (const float*)d_in[2];
    const float* wk  = (const float*)d_in[3];
    const float* fw  = (const float*)d_in[4];
    float* out = (float*)d_out;

    cudaFuncSetAttribute(qv_kernel,    cudaFuncAttributeMaxDynamicSharedMemorySize,
                         QV_SMEM);
    cudaFuncSetAttribute(attn_kernel,  cudaFuncAttributeMaxDynamicSharedMemorySize,
                         ATTN_SMEM);
    cudaFuncSetAttribute(final_kernel, cudaFuncAttributeMaxDynamicSharedMemorySize,
                         (128*130 + 16*128) * 4);

    qv_kernel<<<dim3(32, 64), 256, QV_SMEM>>>(x, wqv);
    k_kernel<<<dim3(TT/16, BB), 256>>>(x, wk);
    attn_kernel<<<dim3(TT/64, HH, BB), 256, ATTN_SMEM>>>(msk);
    final_kernel<<<dim3(TT/16, BB), 256, (128*130 + 16*128) * 4>>>(x, fw, out);
}

// round 12
// speedup vs baseline: 1.1265x; 1.0160x over previous
#include <cuda_runtime.h>
#include <cuda_fp16.h>
#include <math.h>
#include <cstdint>

#define BB 8
#define TT 512
#define DD 128
#define HH 8

typedef unsigned long long u64;

// m16n8k16 f16 MMA, fp32 accumulate (portable PTX, runs on sm_103 HMMA)
__device__ __forceinline__ void mma16816_(float* c, const unsigned* a, const unsigned* b) {
    asm volatile(
        "mma.sync.aligned.m16n8k16.row.col.f32.f16.f16.f32 "
        "{%0,%1,%2,%3}, {%4,%5,%6,%7}, {%8,%9}, {%0,%1,%2,%3};"
        : "+f"(c[0]), "+f"(c[1]), "+f"(c[2]), "+f"(c[3])
        : "r"(a[0]), "r"(a[1]), "r"(a[2]), "r"(a[3]), "r"(b[0]), "r"(b[1]));
}

// |a-b| on fp16x2: HSUB2 (fma pipe) + LOP3 (alu pipe)
__device__ __forceinline__ __half2 habsdiff2_(unsigned a, unsigned b) {
    __half2 d = __hsub2(*(__half2*)&a, *(__half2*)&b);
    unsigned u = (*(unsigned*)&d) & 0x7FFF7FFFu;
    return *(__half2*)&u;
}

// Scratch
__device__ __half g_qh[(size_t)BB*HH*TT*DD];  // q[b][h][t][d] fp16
__device__ __half g_kh[(size_t)BB*HH*TT*DD];  // k[b][h][s][d] fp16 (= x*wk)
__device__ __half g_vT[(size_t)BB*HH*DD*TT];  // vT[b][h][d][s] fp16
__device__ float  g_o [BB*HH*TT*DD];          // o[b][h][t][d] fp32

// ---------------------------------------------------------------------------
// Kernel 1: QV projection via mma.sync (HMMA); q written fp16, v fp16-transposed.
// ---------------------------------------------------------------------------
#define QV_SMEM (2*64*136*2)

__global__ __launch_bounds__(256) void qv_kernel(const float* __restrict__ x,
                                                 const float* __restrict__ w) {
    extern __shared__ __half smh[];
    __half* xsh = smh;            // 64 x 136
    __half* wsh = smh + 64*136;   // 64 x 136
    __shared__ float bsh[64];

    const int tid = threadIdx.x;
    const int warp = tid >> 5, lane = tid & 31;
    const int g = lane >> 2, tg = lane & 3;
    const int mt = warp & 3, ng = warp >> 2;
    const int m0 = blockIdx.y * 64;
    const int n0 = blockIdx.x * 64;

    const float4* xg = (const float4*)(x + (size_t)m0*DD);
    for (int i = tid; i < 64*32; i += 256) {
        int r = i >> 5, c4 = i & 31;
        float4 v = xg[i];
        __half2 h0 = __floats2half2_rn(v.x, v.y);
        __half2 h1 = __floats2half2_rn(v.z, v.w);
        uint2 st; st.x = *(unsigned*)&h0; st.y = *(unsigned*)&h1;
        *(uint2*)&xsh[r*136 + c4*4] = st;
    }
    for (int i = tid; i < 64*64; i += 256) {
        int r = i >> 6, c2 = i & 63;
        const float* wr = w + (size_t)(n0 + r)*129 + c2*2;
        __half2 h = __floats2half2_rn(wr[0], wr[1]);
        *(unsigned*)&wsh[r*136 + c2*2] = *(unsigned*)&h;
    }
    if (tid < 64) bsh[tid] = w[(size_t)(n0 + tid)*129 + 128];
    __syncthreads();

    float oacc[4][4];
#pragma unroll
    for (int nt = 0; nt < 4; nt++)
#pragma unroll
        for (int c = 0; c < 4; c++) oacc[nt][c] = 0.f;

#pragma unroll
    for (int kk = 0; kk < 8; kk++) {
        unsigned af[4];
        const int ar = (mt*16 + g)*136 + kk*16 + tg*2;
        af[0] = *(const unsigned*)&xsh[ar];
        af[1] = *(const unsigned*)&xsh[ar + 8*136];
        af[2] = *(const unsigned*)&xsh[ar + 8];
        af[3] = *(const unsigned*)&xsh[ar + 8*136 + 8];
#pragma unroll
        for (int nt = 0; nt < 4; nt++) {
            const int br = (ng*32 + nt*8 + g)*136 + kk*16 + tg*2;
            unsigned bf[2];
            bf[0] = *(const unsigned*)&wsh[br];
            bf[1] = *(const unsigned*)&wsh[br + 8];
            mma16816_(oacc[nt], af, bf);
        }
    }

#pragma unroll
    for (int nt = 0; nt < 4; nt++) {
        const int col = ng*32 + nt*8 + tg*2;
        oacc[nt][0] += bsh[col];     oacc[nt][1] += bsh[col + 1];
        oacc[nt][2] += bsh[col];     oacc[nt][3] += bsh[col + 1];
    }

    const int bi = m0 >> 9, tb = m0 & 511;
    const int cbase = n0 & 255;
    const int hh = n0 >> 8;

    if (cbase < 128) {
        __half* qg_ = g_qh + ((size_t)(bi*HH + hh)*TT + tb)*DD + cbase;
#pragma unroll
        for (int nt = 0; nt < 4; nt++) {
            const int col = ng*32 + nt*8 + tg*2;
            const int r0 = mt*16 + g;
            __half2 h01 = __floats2half2_rn(oacc[nt][0], oacc[nt][1]);
            __half2 h23 = __floats2half2_rn(oacc[nt][2], oacc[nt][3]);
            *(unsigned*)&qg_[(size_t)r0*DD + col]       = *(unsigned*)&h01;
            *(unsigned*)&qg_[(size_t)(r0 + 8)*DD + col] = *(unsigned*)&h23;
        }
    } else {
        __syncthreads();
        __half* vsm = xsh;             // 64 d-rows x 72 (t stride)
#pragma unroll
        for (int nt = 0; nt < 4; nt++) {
            const int dl = ng*32 + nt*8 + tg*2;
            const int r0 = mt*16 + g;
            vsm[dl*72 + r0]           = __float2half(oacc[nt][0]);
            vsm[(dl + 1)*72 + r0]     = __float2half(oacc[nt][1]);
            vsm[dl*72 + r0 + 8]       = __float2half(oacc[nt][2]);
            vsm[(dl + 1)*72 + r0 + 8] = __float2half(oacc[nt][3]);
        }
        __syncthreads();
        __half* vg = g_vT + ((size_t)(bi*HH + hh)*DD + (cbase - 128))*TT + tb;
        for (int i = tid; i < 1024; i += 256) {
            int row = i >> 4, seg = i & 15;
            uint2 val = *(uint2*)&vsm[row*72 + seg*4];
            *(uint2*)&vg[(size_t)row*TT + seg*4] = val;
        }
    }
}

// ---------------------------------------------------------------------------
// Kernel 1b: k[b][h][s][d] = x[b][s][d] * wk[h][d], fp16. Tiny (~5us).
// ---------------------------------------------------------------------------
__global__ __launch_bounds__(256) void k_kernel(const float* __restrict__ x,
                                                const float* __restrict__ wk) {
    __shared__ float xs[16*128];
    __shared__ float wks[8*128];

    const int b = blockIdx.y, s0 = blockIdx.x * 16;
    const int tid = threadIdx.x;

    const float4* xg = (const float4*)(x + ((size_t)b*TT + s0)*DD);
    for (int i = tid; i < 16*32; i += 256) ((float4*)xs)[i] = xg[i];
    for (int i = tid; i < 8*32; i += 256)  ((float4*)wks)[i] = ((const float4*)wk)[i];
    __syncthreads();

    for (int i = tid; i < 16*8*64; i += 256) {
        int d2 = i & 63, hh = (i >> 6) & 7, sl = i >> 9;
        float2 xv = *(const float2*)&xs[sl*128 + d2*2];
        float2 wv = *(const float2*)&wks[hh*128 + d2*2];
        __half2 h = __floats2half2_rn(xv.x*wv.x, xv.y*wv.y);
        *(unsigned*)&g_kh[((size_t)(b*HH + hh)*TT + s0 + sl)*DD + d2*2] = *(unsigned*)&h;
    }
}

// ---------------------------------------------------------------------------
// Kernel 2: fused L1 attention (unchanged from R11 — 248us best config)
// ---------------------------------------------------------------------------
#define SSTRIDE 520
#define OFF_QH 133120
#define OFF_KH 150528
#define OFF_VT 133120
#define ATTN_SMEM 167936

__global__ __launch_bounds__(256) void attn_kernel(const float* __restrict__ msk) {
    extern __shared__ char smc[];
    float*  Ssh = (float*)smc;
    __half* qsh = (__half*)(smc + OFF_QH);
    __half* ksh = (__half*)(smc + OFF_KH);

    const int b  = blockIdx.z, h = blockIdx.y;
    const int t0 = blockIdx.x * 64;
    const int tid = threadIdx.x;
    const int tx  = tid & 15, ty = tid >> 4;

    const uint4* khg = (const uint4*)(g_kh + ((size_t)(b*HH + h))*TT*DD);

    const uint4* qg = (const uint4*)(g_qh + (((size_t)(b*HH + h))*TT + t0)*DD);
#pragma unroll
    for (int u = 0; u < 4; u++) {
        int i = tid + u*256;
        int r = i >> 4, kg = i & 15;
        *(uint4*)&qsh[r*136 + kg*8] = qg[i];
    }

    const float NEG_ISQ = -0.08838834764831845f;  // -1/sqrt(128)

    uint4 kreg[4];
#pragma unroll
    for (int u = 0; u < 4; u++) kreg[u] = khg[tid + u*256];

    // ---------------- Phase 1: score tiles ----------------
    for (int sc = 0; sc < 8; sc++) {
        const int s0 = sc * 64;
#pragma unroll
        for (int u = 0; u < 4; u++) {
            int i = tid + u*256;
            int r = i >> 4, kg = i & 15;
            *(uint4*)&ksh[r*136 + kg*8] = kreg[u];
        }
        __syncthreads();

        if (sc + 1 < 8) {
#pragma unroll
            for (int u = 0; u < 4; u++) kreg[u] = khg[(sc + 1)*1024 + tid + u*256];
        }

        float facc[4][4];
#pragma unroll
        for (int i = 0; i < 4; i++)
#pragma unroll
            for (int j = 0; j < 4; j++) facc[i][j] = 0.f;

#pragma unroll
        for (int hf = 0; hf < 2; hf++) {
            __half2 hacc[4][4];
            const __half2 hz = __float2half2_rn(0.f);
#pragma unroll
            for (int i = 0; i < 4; i++)
#pragma unroll
                for (int j = 0; j < 4; j++) hacc[i][j] = hz;

#pragma unroll
            for (int dp = 0; dp < 64; dp += 8) {
                const int d = hf*64 + dp;
                uint4 qv[4], kv[4];
#pragma unroll
                for (int i = 0; i < 4; i++) qv[i] = *(const uint4*)&qsh[(ty*4 + i)*136 + d];
#pragma unroll
                for (int j = 0; j < 4; j++) kv[j] = *(const uint4*)&ksh[(tx + 16*j)*136 + d];
#pragma unroll
                for (int i = 0; i < 4; i++)
#pragma unroll
                    for (int j = 0; j < 4; j++) {
                        __half2 a = hacc[i][j];
                        a = __hadd2(a, habsdiff2_(qv[i].x, kv[j].x));
                        a = __hadd2(a, habsdiff2_(qv[i].y, kv[j].y));
                        a = __hadd2(a, habsdiff2_(qv[i].z, kv[j].z));
                        a = __hadd2(a, habsdiff2_(qv[i].w, kv[j].w));
                        hacc[i][j] = a;
                    }
            }
#pragma unroll
            for (int i = 0; i < 4; i++)
#pragma unroll
                for (int j = 0; j < 4; j++) {
                    float2 f = __half22float2(hacc[i][j]);
                    facc[i][j] += f.x;
                    facc[i][j] += f.y;
                }
        }

#pragma unroll
        for (int i = 0; i < 4; i++)
#pragma unroll
            for (int j = 0; j < 4; j++)
                Ssh[(ty*4 + i)*SSTRIDE + s0 + tx + 16*j] = facc[i][j] * NEG_ISQ;
        __syncthreads();
    }

    // ---------------- Phase 2: row softmax + mask ----------------
    const int warp = tid >> 5, lane = tid & 31;
    for (int r = warp; r < 64; r += 8) {
        float* row = Ssh + r*SSTRIDE;
        float vals[16];
        float m = -1e30f;
#pragma unroll
        for (int i = 0; i < 16; i++) { vals[i] = row[lane + i*32]; m = fmaxf(m, vals[i]); }
#pragma unroll
        for (int o = 16; o > 0; o >>= 1) m = fmaxf(m, __shfl_xor_sync(0xffffffffu, m, o));
        float sum = 0.f;
#pragma unroll
        for (int i = 0; i < 16; i++) { vals[i] = __expf(vals[i] - m); sum += vals[i]; }
#pragma unroll
        for (int o = 16; o > 0; o >>= 1) sum += __shfl_xor_sync(0xffffffffu, sum, o);
        float inv = 1.f / sum;
        const float* mrow = msk + ((size_t)(h*TT + t0 + r))*TT;
#pragma unroll
        for (int i = 0; i < 16; i++)
            row[lane + i*32] = vals[i] * inv * mrow[lane + i*32];
    }
    __syncthreads();

    // ---------------- Phase 3: O = P @ V via mma.sync ----------------
    __half* vTsh = (__half*)(smc + OFF_VT);
    const __half* vTg = g_vT + ((size_t)(b*HH + h))*DD*TT;
    const int mt = warp & 3, ng = warp >> 2;
    const int g = lane >> 2, tg = lane & 3;

    float oacc[8][4];
#pragma unroll
    for (int nt = 0; nt < 8; nt++)
#pragma unroll
        for (int c = 0; c < 4; c++) oacc[nt][c] = 0.f;

    for (int sc = 0; sc < 4; sc++) {
        const int s0 = sc * 128;
        for (int i = tid; i < 2048; i += 256) {
            int r = i >> 4, kg = i & 15;
            uint4 val = *(const uint4*)(vTg + (size_t)r*TT + s0 + kg*8);
            *(uint4*)&vTsh[r*136 + kg*8] = val;
        }
        __syncthreads();

#pragma unroll
        for (int kk = 0; kk < 8; kk++) {
            const int ar = (mt*16 + g)*SSTRIDE + s0 + kk*16 + tg*2;
            float2 a01 = *(const float2*)&Ssh[ar];
            float2 a23 = *(const float2*)&Ssh[ar + 8*SSTRIDE];
            float2 a45 = *(const float2*)&Ssh[ar + 8];
            float2 a67 = *(const float2*)&Ssh[ar + 8*SSTRIDE + 8];
            unsigned af[4];
            __half2 h0 = __floats2half2_rn(a01.x, a01.y); af[0] = *(unsigned*)&h0;
            __half2 h1 = __floats2half2_rn(a23.x, a23.y); af[1] = *(unsigned*)&h1;
            __half2 h2 = __floats2half2_rn(a45.x, a45.y); af[2] = *(unsigned*)&h2;
            __half2 h3 = __floats2half2_rn(a67.x, a67.y); af[3] = *(unsigned*)&h3;

            const int kb = kk*16 + tg*2;
#pragma unroll
            for (int nt = 0; nt < 8; nt++) {
                int row = ng*64 + nt*8 + g;
                unsigned bf[2];
                bf[0] = *(const unsigned*)&vTsh[row*136 + kb];
                bf[1] = *(const unsigned*)&vTsh[row*136 + kb + 8];
                mma16816_(oacc[nt], af, bf);
            }
        }
        __syncthreads();
    }

    float* og = g_o + (((size_t)(b*HH + h))*TT + t0)*DD;
#pragma unroll
    for (int nt = 0; nt < 8; nt++) {
        int d = ng*64 + nt*8 + tg*2;
        int r0 = mt*16 + g;
        *(float2*)&og[(size_t)r0*DD + d]       = make_float2(oacc[nt][0], oacc[nt][1]);
        *(float2*)&og[(size_t)(r0 + 8)*DD + d] = make_float2(oacc[nt][2], oacc[nt][3]);
    }
}

// ---------------------------------------------------------------------------
// Kernel 3: head-reduce + quickGELU, then fanout GEMM via mma.sync (HMMA).
// out[t][o] = x[t][o] + sum_i fanout[o][i]*yo[t][i] + bias[o]
// A = yo fp16 [16 x 128] row-major, B = W fp16 [128 o][128 i] k-contiguous.
// Warp w covers o-cols [w*16, w*16+16).
// smem: Wh 128x136 fp16 (34816B) | yosh 16x136 fp16 (4352B) | bias 128 f32
// ---------------------------------------------------------------------------
#define FIN_SMEM (128*136*2 + 16*136*2 + 512)

__global__ __launch_bounds__(256) void final_kernel(const float* __restrict__ x,
                                                    const float* __restrict__ fw,
                                                    float* __restrict__ out) {
    extern __shared__ char fsm[];
    __half* Wh   = (__half*)fsm;                      // 128 x 136
    __half* yosh = (__half*)(fsm + 128*136*2);        // 16 x 136
    float*  bsh  = (float*)(fsm + 128*136*2 + 16*136*2);

    const int b = blockIdx.y, t0 = blockIdx.x * 16;
    const int tid = threadIdx.x;
    const int warp = tid >> 5, lane = tid & 31;
    const int g = lane >> 2, tg = lane & 3;

    // stage W fp32 -> fp16 (row length 129 in gmem)
    for (int i = tid; i < 128*64; i += 256) {
        int r = i >> 6, c2 = i & 63;
        const float* wr = fw + (size_t)r*129 + c2*2;
        __half2 h = __floats2half2_rn(wr[0], wr[1]);
        *(unsigned*)&Wh[r*136 + c2*2] = *(unsigned*)&h;
    }
    if (tid < 128) bsh[tid] = fw[(size_t)tid*129 + 128];

    // h-reduce + quickGELU -> yosh fp16
    for (int i = tid; i < 16*128; i += 256) {
        int r = i >> 7, dd = i & 127;
        float bo = 0.f;
#pragma unroll
        for (int h = 0; h < HH; h++)
            bo += g_o[(((size_t)(b*HH + h))*TT + t0 + r)*DD + dd];
        float z  = bo + 4.5f;
        float sg = 1.f / (1.f + __expf(-1.702f * z));
        yosh[r*136 + dd] = __float2half(z*sg - 4.5f);
    }
    __syncthreads();

    float acc[2][4];
#pragma unroll
    for (int nt = 0; nt < 2; nt++)
#pragma unroll
        for (int c = 0; c < 4; c++) acc[nt][c] = 0.f;

#pragma unroll
    for (int kk = 0; kk < 8; kk++) {
        unsigned af[4];
        const int ar = g*136 + kk*16 + tg*2;
        af[0] = *(const unsigned*)&yosh[ar];
        af[1] = *(const unsigned*)&yosh[ar + 8*136];
        af[2] = *(const unsigned*)&yosh[ar + 8];
        af[3] = *(const unsigned*)&yosh[ar + 8*136 + 8];
#pragma unroll
        for (int nt = 0; nt < 2; nt++) {
            const int br = (warp*16 + nt*8 + g)*136 + kk*16 + tg*2;
            unsigned bf[2];
            bf[0] = *(const unsigned*)&Wh[br];
            bf[1] = *(const unsigned*)&Wh[br + 8];
            mma16816_(acc[nt], af, bf);
        }
    }

#pragma unroll
    for (int nt = 0; nt < 2; nt++) {
        const int col = warp*16 + nt*8 + tg*2;
        const float b0 = bsh[col], b1 = bsh[col + 1];
        size_t i0 = ((size_t)b*TT + t0 + g)*DD + col;
        size_t i1 = ((size_t)b*TT + t0 + g + 8)*DD + col;
        out[i0]     = x[i0]     + acc[nt][0] + b0;
        out[i0 + 1] = x[i0 + 1] + acc[nt][1] + b1;
        out[i1]     = x[i1]     + acc[nt][2] + b0;
        out[i1 + 1] = x[i1 + 1] + acc[nt][3] + b1;
    }
}

// ---------------------------------------------------------------------------
extern "C" void kernel_launch(void* const* d_in, const int* in_sizes, int n_in,
                              void* d_out, int out_size) {
    const float* x   = (const float*)d_in[0];
    const float* msk = (const float*)d_in[1];
    const float* wqv = (const float*)d_in[2];
    const float* wk  = (const float*)d_in[3];
    const float* fw  = (const float*)d_in[4];
    float* out = (float*)d_out;

    cudaFuncSetAttribute(qv_kernel,    cudaFuncAttributeMaxDynamicSharedMemorySize,
                         QV_SMEM);
    cudaFuncSetAttribute(attn_kernel,  cudaFuncAttributeMaxDynamicSharedMemorySize,
                         ATTN_SMEM);
    cudaFuncSetAttribute(final_kernel, cudaFuncAttributeMaxDynamicSharedMemorySize,
                         FIN_SMEM);

    qv_kernel<<<dim3(32, 64), 256, QV_SMEM>>>(x, wqv);
    k_kernel<<<dim3(TT/16, BB), 256>>>(x, wk);
    attn_kernel<<<dim3(TT/64, HH, BB), 256, ATTN_SMEM>>>(msk);
    final_kernel<<<dim3(TT/16, BB), 256, FIN_SMEM>>>(x, fw, out);
}

// round 13
// speedup vs baseline: 1.2762x; 1.1329x over previous
#include <cuda_runtime.h>
#include <cuda_fp16.h>
#include <math.h>
#include <cstdint>

#define BB 8
#define TT 512
#define DD 128
#define HH 8

typedef unsigned long long u64;

// m16n8k16 f16 MMA, fp32 accumulate (portable PTX, runs on sm_103 HMMA)
__device__ __forceinline__ void mma16816_(float* c, const unsigned* a, const unsigned* b) {
    asm volatile(
        "mma.sync.aligned.m16n8k16.row.col.f32.f16.f16.f32 "
        "{%0,%1,%2,%3}, {%4,%5,%6,%7}, {%8,%9}, {%0,%1,%2,%3};"
        : "+f"(c[0]), "+f"(c[1]), "+f"(c[2]), "+f"(c[3])
        : "r"(a[0]), "r"(a[1]), "r"(a[2]), "r"(a[3]), "r"(b[0]), "r"(b[1]));
}

// |a-b| on fp16x2: HSUB2 (fma pipe) + LOP3 (alu pipe)
__device__ __forceinline__ __half2 habsdiff2_(unsigned a, unsigned b) {
    __half2 d = __hsub2(*(__half2*)&a, *(__half2*)&b);
    unsigned u = (*(unsigned*)&d) & 0x7FFF7FFFu;
    return *(__half2*)&u;
}

// Scratch
__device__ __half g_qh[(size_t)BB*HH*TT*DD];  // q[b][h][t][d] fp16
__device__ __half g_kh[(size_t)BB*HH*TT*DD];  // k[b][h][s][d] fp16 (= x*wk)
__device__ __half g_vT[(size_t)BB*HH*DD*TT];  // vT[b][h][d][s] fp16
__device__ float  g_o [BB*HH*TT*DD];          // o[b][h][t][d] fp32

// ---------------------------------------------------------------------------
// Kernel 1: QV projection via mma.sync (HMMA); q written fp16, v fp16-transposed.
// ---------------------------------------------------------------------------
#define QV_SMEM (2*64*136*2)

__global__ __launch_bounds__(256) void qv_kernel(const float* __restrict__ x,
                                                 const float* __restrict__ w) {
    extern __shared__ __half smh[];
    __half* xsh = smh;            // 64 x 136
    __half* wsh = smh + 64*136;   // 64 x 136
    __shared__ float bsh[64];

    const int tid = threadIdx.x;
    const int warp = tid >> 5, lane = tid & 31;
    const int g = lane >> 2, tg = lane & 3;
    const int mt = warp & 3, ng = warp >> 2;
    const int m0 = blockIdx.y * 64;
    const int n0 = blockIdx.x * 64;

    const float4* xg = (const float4*)(x + (size_t)m0*DD);
    for (int i = tid; i < 64*32; i += 256) {
        int r = i >> 5, c4 = i & 31;
        float4 v = xg[i];
        __half2 h0 = __floats2half2_rn(v.x, v.y);
        __half2 h1 = __floats2half2_rn(v.z, v.w);
        uint2 st; st.x = *(unsigned*)&h0; st.y = *(unsigned*)&h1;
        *(uint2*)&xsh[r*136 + c4*4] = st;
    }
    for (int i = tid; i < 64*64; i += 256) {
        int r = i >> 6, c2 = i & 63;
        const float* wr = w + (size_t)(n0 + r)*129 + c2*2;
        __half2 h = __floats2half2_rn(wr[0], wr[1]);
        *(unsigned*)&wsh[r*136 + c2*2] = *(unsigned*)&h;
    }
    if (tid < 64) bsh[tid] = w[(size_t)(n0 + tid)*129 + 128];
    __syncthreads();

    float oacc[4][4];
#pragma unroll
    for (int nt = 0; nt < 4; nt++)
#pragma unroll
        for (int c = 0; c < 4; c++) oacc[nt][c] = 0.f;

#pragma unroll
    for (int kk = 0; kk < 8; kk++) {
        unsigned af[4];
        const int ar = (mt*16 + g)*136 + kk*16 + tg*2;
        af[0] = *(const unsigned*)&xsh[ar];
        af[1] = *(const unsigned*)&xsh[ar + 8*136];
        af[2] = *(const unsigned*)&xsh[ar + 8];
        af[3] = *(const unsigned*)&xsh[ar + 8*136 + 8];
#pragma unroll
        for (int nt = 0; nt < 4; nt++) {
            const int br = (ng*32 + nt*8 + g)*136 + kk*16 + tg*2;
            unsigned bf[2];
            bf[0] = *(const unsigned*)&wsh[br];
            bf[1] = *(const unsigned*)&wsh[br + 8];
            mma16816_(oacc[nt], af, bf);
        }
    }

#pragma unroll
    for (int nt = 0; nt < 4; nt++) {
        const int col = ng*32 + nt*8 + tg*2;
        oacc[nt][0] += bsh[col];     oacc[nt][1] += bsh[col + 1];
        oacc[nt][2] += bsh[col];     oacc[nt][3] += bsh[col + 1];
    }

    const int bi = m0 >> 9, tb = m0 & 511;
    const int cbase = n0 & 255;
    const int hh = n0 >> 8;

    if (cbase < 128) {
        __half* qg_ = g_qh + ((size_t)(bi*HH + hh)*TT + tb)*DD + cbase;
#pragma unroll
        for (int nt = 0; nt < 4; nt++) {
            const int col = ng*32 + nt*8 + tg*2;
            const int r0 = mt*16 + g;
            __half2 h01 = __floats2half2_rn(oacc[nt][0], oacc[nt][1]);
            __half2 h23 = __floats2half2_rn(oacc[nt][2], oacc[nt][3]);
            *(unsigned*)&qg_[(size_t)r0*DD + col]       = *(unsigned*)&h01;
            *(unsigned*)&qg_[(size_t)(r0 + 8)*DD + col] = *(unsigned*)&h23;
        }
    } else {
        __syncthreads();
        __half* vsm = xsh;             // 64 d-rows x 72 (t stride)
#pragma unroll
        for (int nt = 0; nt < 4; nt++) {
            const int dl = ng*32 + nt*8 + tg*2;
            const int r0 = mt*16 + g;
            vsm[dl*72 + r0]           = __float2half(oacc[nt][0]);
            vsm[(dl + 1)*72 + r0]     = __float2half(oacc[nt][1]);
            vsm[dl*72 + r0 + 8]       = __float2half(oacc[nt][2]);
            vsm[(dl + 1)*72 + r0 + 8] = __float2half(oacc[nt][3]);
        }
        __syncthreads();
        __half* vg = g_vT + ((size_t)(bi*HH + hh)*DD + (cbase - 128))*TT + tb;
        for (int i = tid; i < 1024; i += 256) {
            int row = i >> 4, seg = i & 15;
            uint2 val = *(uint2*)&vsm[row*72 + seg*4];
            *(uint2*)&vg[(size_t)row*TT + seg*4] = val;
        }
    }
}

// ---------------------------------------------------------------------------
// Kernel 1b: k[b][h][s][d] = x[b][s][d] * wk[h][d], fp16. Tiny (~5us).
// ---------------------------------------------------------------------------
__global__ __launch_bounds__(256) void k_kernel(const float* __restrict__ x,
                                                const float* __restrict__ wk) {
    __shared__ float xs[16*128];
    __shared__ float wks[8*128];

    const int b = blockIdx.y, s0 = blockIdx.x * 16;
    const int tid = threadIdx.x;

    const float4* xg = (const float4*)(x + ((size_t)b*TT + s0)*DD);
    for (int i = tid; i < 16*32; i += 256) ((float4*)xs)[i] = xg[i];
    for (int i = tid; i < 8*32; i += 256)  ((float4*)wks)[i] = ((const float4*)wk)[i];
    __syncthreads();

    for (int i = tid; i < 16*8*64; i += 256) {
        int d2 = i & 63, hh = (i >> 6) & 7, sl = i >> 9;
        float2 xv = *(const float2*)&xs[sl*128 + d2*2];
        float2 wv = *(const float2*)&wks[hh*128 + d2*2];
        __half2 h = __floats2half2_rn(xv.x*wv.x, xv.y*wv.y);
        *(unsigned*)&g_kh[((size_t)(b*HH + hh)*TT + s0 + sl)*DD + d2*2] = *(unsigned*)&h;
    }
}

// ---------------------------------------------------------------------------
// Kernel 2: fused L1 attention. S/P stored fp16 -> 101KB smem -> 2 CTAs/SM.
// smem (bytes):
//   [0,66560)        Ssh fp16 64 x 520 (stride 520 halves: A-frag loads conflict-free)
//   [66560,83968)    qsh fp16 64x136   | phase3 vTsh fp16 128x136 overlays
//   [83968,101376)   ksh fp16 64x136   |   [66560,101376)
// ---------------------------------------------------------------------------
#define SSTRIDE 520
#define OFF_QH 66560
#define OFF_KH 83968
#define OFF_VT 66560
#define ATTN_SMEM 101376

__global__ __launch_bounds__(256) void attn_kernel(const float* __restrict__ msk) {
    extern __shared__ char smc[];
    __half* Ssh = (__half*)smc;
    __half* qsh = (__half*)(smc + OFF_QH);
    __half* ksh = (__half*)(smc + OFF_KH);

    const int b  = blockIdx.z, h = blockIdx.y;
    const int t0 = blockIdx.x * 64;
    const int tid = threadIdx.x;
    const int tx  = tid & 15, ty = tid >> 4;

    const uint4* khg = (const uint4*)(g_kh + ((size_t)(b*HH + h))*TT*DD);

    const uint4* qg = (const uint4*)(g_qh + (((size_t)(b*HH + h))*TT + t0)*DD);
#pragma unroll
    for (int u = 0; u < 4; u++) {
        int i = tid + u*256;
        int r = i >> 4, kg = i & 15;
        *(uint4*)&qsh[r*136 + kg*8] = qg[i];
    }

    const float NEG_ISQ = -0.08838834764831845f;  // -1/sqrt(128)

    uint4 kreg[4];
#pragma unroll
    for (int u = 0; u < 4; u++) kreg[u] = khg[tid + u*256];

    // ---------------- Phase 1: score tiles ----------------
    for (int sc = 0; sc < 8; sc++) {
        const int s0 = sc * 64;
#pragma unroll
        for (int u = 0; u < 4; u++) {
            int i = tid + u*256;
            int r = i >> 4, kg = i & 15;
            *(uint4*)&ksh[r*136 + kg*8] = kreg[u];
        }
        __syncthreads();

        if (sc + 1 < 8) {
#pragma unroll
            for (int u = 0; u < 4; u++) kreg[u] = khg[(sc + 1)*1024 + tid + u*256];
        }

        float facc[4][4];
#pragma unroll
        for (int i = 0; i < 4; i++)
#pragma unroll
            for (int j = 0; j < 4; j++) facc[i][j] = 0.f;

#pragma unroll
        for (int hf = 0; hf < 2; hf++) {
            __half2 hacc[4][4];
            const __half2 hz = __float2half2_rn(0.f);
#pragma unroll
            for (int i = 0; i < 4; i++)
#pragma unroll
                for (int j = 0; j < 4; j++) hacc[i][j] = hz;

#pragma unroll
            for (int dp = 0; dp < 64; dp += 8) {
                const int d = hf*64 + dp;
                uint4 qv[4], kv[4];
#pragma unroll
                for (int i = 0; i < 4; i++) qv[i] = *(const uint4*)&qsh[(ty*4 + i)*136 + d];
#pragma unroll
                for (int j = 0; j < 4; j++) kv[j] = *(const uint4*)&ksh[(tx + 16*j)*136 + d];
#pragma unroll
                for (int i = 0; i < 4; i++)
#pragma unroll
                    for (int j = 0; j < 4; j++) {
                        __half2 a = hacc[i][j];
                        a = __hadd2(a, habsdiff2_(qv[i].x, kv[j].x));
                        a = __hadd2(a, habsdiff2_(qv[i].y, kv[j].y));
                        a = __hadd2(a, habsdiff2_(qv[i].z, kv[j].z));
                        a = __hadd2(a, habsdiff2_(qv[i].w, kv[j].w));
                        hacc[i][j] = a;
                    }
            }
#pragma unroll
            for (int i = 0; i < 4; i++)
#pragma unroll
                for (int j = 0; j < 4; j++) {
                    float2 f = __half22float2(hacc[i][j]);
                    facc[i][j] += f.x;
                    facc[i][j] += f.y;
                }
        }

#pragma unroll
        for (int i = 0; i < 4; i++)
#pragma unroll
            for (int j = 0; j < 4; j++)
                Ssh[(ty*4 + i)*SSTRIDE + s0 + tx + 16*j] =
                    __float2half(facc[i][j] * NEG_ISQ);
        __syncthreads();
    }

    // ---------------- Phase 2: row softmax + mask (fp32 in registers) ------
    const int warp = tid >> 5, lane = tid & 31;
    for (int r = warp; r < 64; r += 8) {
        __half* row = Ssh + r*SSTRIDE;
        float vals[16];
        float m = -1e30f;
#pragma unroll
        for (int i = 0; i < 16; i++) {
            vals[i] = __half2float(row[lane + i*32]);
            m = fmaxf(m, vals[i]);
        }
#pragma unroll
        for (int o = 16; o > 0; o >>= 1) m = fmaxf(m, __shfl_xor_sync(0xffffffffu, m, o));
        float sum = 0.f;
#pragma unroll
        for (int i = 0; i < 16; i++) { vals[i] = __expf(vals[i] - m); sum += vals[i]; }
#pragma unroll
        for (int o = 16; o > 0; o >>= 1) sum += __shfl_xor_sync(0xffffffffu, sum, o);
        float inv = 1.f / sum;
        const float* mrow = msk + ((size_t)(h*TT + t0 + r))*TT;
#pragma unroll
        for (int i = 0; i < 16; i++)
            row[lane + i*32] = __float2half(vals[i] * inv * mrow[lane + i*32]);
    }
    __syncthreads();

    // ---------------- Phase 3: O = P @ V via mma.sync (A = fp16 S direct) --
    __half* vTsh = (__half*)(smc + OFF_VT);
    const __half* vTg = g_vT + ((size_t)(b*HH + h))*DD*TT;
    const int mt = warp & 3, ng = warp >> 2;
    const int g = lane >> 2, tg = lane & 3;

    float oacc[8][4];
#pragma unroll
    for (int nt = 0; nt < 8; nt++)
#pragma unroll
        for (int c = 0; c < 4; c++) oacc[nt][c] = 0.f;

    for (int sc = 0; sc < 4; sc++) {
        const int s0 = sc * 128;
        for (int i = tid; i < 2048; i += 256) {
            int r = i >> 4, kg = i & 15;
            uint4 val = *(const uint4*)(vTg + (size_t)r*TT + s0 + kg*8);
            *(uint4*)&vTsh[r*136 + kg*8] = val;
        }
        __syncthreads();

#pragma unroll
        for (int kk = 0; kk < 8; kk++) {
            const int ar = (mt*16 + g)*SSTRIDE + s0 + kk*16 + tg*2;
            unsigned af[4];
            af[0] = *(const unsigned*)&Ssh[ar];
            af[1] = *(const unsigned*)&Ssh[ar + 8*SSTRIDE];
            af[2] = *(const unsigned*)&Ssh[ar + 8];
            af[3] = *(const unsigned*)&Ssh[ar + 8*SSTRIDE + 8];

            const int kb = kk*16 + tg*2;
#pragma unroll
            for (int nt = 0; nt < 8; nt++) {
                int row = ng*64 + nt*8 + g;
                unsigned bf[2];
                bf[0] = *(const unsigned*)&vTsh[row*136 + kb];
                bf[1] = *(const unsigned*)&vTsh[row*136 + kb + 8];
                mma16816_(oacc[nt], af, bf);
            }
        }
        __syncthreads();
    }

    float* og = g_o + (((size_t)(b*HH + h))*TT + t0)*DD;
#pragma unroll
    for (int nt = 0; nt < 8; nt++) {
        int d = ng*64 + nt*8 + tg*2;
        int r0 = mt*16 + g;
        *(float2*)&og[(size_t)r0*DD + d]       = make_float2(oacc[nt][0], oacc[nt][1]);
        *(float2*)&og[(size_t)(r0 + 8)*DD + d] = make_float2(oacc[nt][2], oacc[nt][3]);
    }
}

// ---------------------------------------------------------------------------
// Kernel 3: head-reduce + quickGELU + fanout HMMA + residual (R12 version)
// ---------------------------------------------------------------------------
#define FIN_SMEM (128*136*2 + 16*136*2 + 512)

__global__ __launch_bounds__(256) void final_kernel(const float* __restrict__ x,
                                                    const float* __restrict__ fw,
                                                    float* __restrict__ out) {
    extern __shared__ char fsm[];
    __half* Wh   = (__half*)fsm;                      // 128 x 136
    __half* yosh = (__half*)(fsm + 128*136*2);        // 16 x 136
    float*  bsh  = (float*)(fsm + 128*136*2 + 16*136*2);

    const int b = blockIdx.y, t0 = blockIdx.x * 16;
    const int tid = threadIdx.x;
    const int warp = tid >> 5, lane = tid & 31;
    const int g = lane >> 2, tg = lane & 3;

    for (int i = tid; i < 128*64; i += 256) {
        int r = i >> 6, c2 = i & 63;
        const float* wr = fw + (size_t)r*129 + c2*2;
        __half2 h = __floats2half2_rn(wr[0], wr[1]);
        *(unsigned*)&Wh[r*136 + c2*2] = *(unsigned*)&h;
    }
    if (tid < 128) bsh[tid] = fw[(size_t)tid*129 + 128];

    for (int i = tid; i < 16*128; i += 256) {
        int r = i >> 7, dd = i & 127;
        float bo = 0.f;
#pragma unroll
        for (int h = 0; h < HH; h++)
            bo += g_o[(((size_t)(b*HH + h))*TT + t0 + r)*DD + dd];
        float z  = bo + 4.5f;
        float sg = 1.f / (1.f + __expf(-1.702f * z));
        yosh[r*136 + dd] = __float2half(z*sg - 4.5f);
    }
    __syncthreads();

    float acc[2][4];
#pragma unroll
    for (int nt = 0; nt < 2; nt++)
#pragma unroll
        for (int c = 0; c < 4; c++) acc[nt][c] = 0.f;

#pragma unroll
    for (int kk = 0; kk < 8; kk++) {
        unsigned af[4];
        const int ar = g*136 + kk*16 + tg*2;
        af[0] = *(const unsigned*)&yosh[ar];
        af[1] = *(const unsigned*)&yosh[ar + 8*136];
        af[2] = *(const unsigned*)&yosh[ar + 8];
        af[3] = *(const unsigned*)&yosh[ar + 8*136 + 8];
#pragma unroll
        for (int nt = 0; nt < 2; nt++) {
            const int br = (warp*16 + nt*8 + g)*136 + kk*16 + tg*2;
            unsigned bf[2];
            bf[0] = *(const unsigned*)&Wh[br];
            bf[1] = *(const unsigned*)&Wh[br + 8];
            mma16816_(acc[nt], af, bf);
        }
    }

#pragma unroll
    for (int nt = 0; nt < 2; nt++) {
        const int col = warp*16 + nt*8 + tg*2;
        const float b0 = bsh[col], b1 = bsh[col + 1];
        size_t i0 = ((size_t)b*TT + t0 + g)*DD + col;
        size_t i1 = ((size_t)b*TT + t0 + g + 8)*DD + col;
        out[i0]     = x[i0]     + acc[nt][0] + b0;
        out[i0 + 1] = x[i0 + 1] + acc[nt][1] + b1;
        out[i1]     = x[i1]     + acc[nt][2] + b0;
        out[i1 + 1] = x[i1 + 1] + acc[nt][3] + b1;
    }
}

// ---------------------------------------------------------------------------
extern "C" void kernel_launch(void* const* d_in, const int* in_sizes, int n_in,
                              void* d_out, int out_size) {
    const float* x   = (const float*)d_in[0];
    const float* msk = (const float*)d_in[1];
    const float* wqv = (const float*)d_in[2];
    const float* wk  = (const float*)d_in[3];
    const float* fw  = (const float*)d_in[4];
    float* out = (float*)d_out;

    cudaFuncSetAttribute(qv_kernel,    cudaFuncAttributeMaxDynamicSharedMemorySize,
                         QV_SMEM);
    cudaFuncSetAttribute(attn_kernel,  cudaFuncAttributeMaxDynamicSharedMemorySize,
                         ATTN_SMEM);
    cudaFuncSetAttribute(final_kernel, cudaFuncAttributeMaxDynamicSharedMemorySize,
                         FIN_SMEM);

    qv_kernel<<<dim3(32, 64), 256, QV_SMEM>>>(x, wqv);
    k_kernel<<<dim3(TT/16, BB), 256>>>(x, wk);
    attn_kernel<<<dim3(TT/64, HH, BB), 256, ATTN_SMEM>>>(msk);
    final_kernel<<<dim3(TT/16, BB), 256, FIN_SMEM>>>(x, fw, out);
}

// round 14
// speedup vs baseline: 2.2296x; 1.7471x over previous
#include <cuda_runtime.h>
#include <cuda_fp16.h>
#include <math.h>
#include <cstdint>

#define BB 8
#define TT 512
#define DD 128
#define HH 8

// int8 quantization scale for q/k distance path
#define QINV  72.0f
// logit constant: -(1/QINV)/sqrt(128)
#define CNEG  (-0.0012276274f)

typedef unsigned long long u64;

// m16n8k16 f16 MMA, fp32 accumulate (portable PTX, runs on sm_103 HMMA)
__device__ __forceinline__ void mma16816_(float* c, const unsigned* a, const unsigned* b) {
    asm volatile(
        "mma.sync.aligned.m16n8k16.row.col.f32.f16.f16.f32 "
        "{%0,%1,%2,%3}, {%4,%5,%6,%7}, {%8,%9}, {%0,%1,%2,%3};"
        : "+f"(c[0]), "+f"(c[1]), "+f"(c[2]), "+f"(c[3])
        : "r"(a[0]), "r"(a[1]), "r"(a[2]), "r"(a[3]), "r"(b[0]), "r"(b[1]));
}

// SAD: d = c + sum_i |sbyte_i(a) - sbyte_i(b)|  (single HW instruction)
__device__ __forceinline__ unsigned vad4_(unsigned a, unsigned b, unsigned c) {
    unsigned d;
    asm("vabsdiff4.u32.s32.s32.add %0, %1, %2, %3;" : "=r"(d) : "r"(a), "r"(b), "r"(c));
    return d;
}

__device__ __forceinline__ int q1_(float f) {
    int i = __float2int_rn(f * QINV);
    return max(-127, min(127, i));
}
__device__ __forceinline__ unsigned pack4i_(int a, int b, int c, int d) {
    return (unsigned)(a & 255) | ((unsigned)(b & 255) << 8) |
           ((unsigned)(c & 255) << 16) | ((unsigned)(d & 255) << 24);
}

// Scratch
__device__ __half g_qh[(size_t)BB*HH*TT*DD];               // q[b][h][t][d] fp16
__device__ __align__(16) signed char g_k8[(size_t)BB*HH*TT*DD]; // k int8 (x*wk, scale 1/QINV)
__device__ __half g_vT[(size_t)BB*HH*DD*TT];               // vT[b][h][d][s] fp16
__device__ float  g_o [BB*HH*TT*DD];                       // o[b][h][t][d] fp32

// ---------------------------------------------------------------------------
// Kernel 1: QV projection via mma.sync (HMMA); q written fp16, v fp16-transposed.
// (unchanged from R13)
// ---------------------------------------------------------------------------
#define QV_SMEM (2*64*136*2)

__global__ __launch_bounds__(256) void qv_kernel(const float* __restrict__ x,
                                                 const float* __restrict__ w) {
    extern __shared__ __half smh[];
    __half* xsh = smh;            // 64 x 136
    __half* wsh = smh + 64*136;   // 64 x 136
    __shared__ float bsh[64];

    const int tid = threadIdx.x;
    const int warp = tid >> 5, lane = tid & 31;
    const int g = lane >> 2, tg = lane & 3;
    const int mt = warp & 3, ng = warp >> 2;
    const int m0 = blockIdx.y * 64;
    const int n0 = blockIdx.x * 64;

    const float4* xg = (const float4*)(x + (size_t)m0*DD);
    for (int i = tid; i < 64*32; i += 256) {
        int r = i >> 5, c4 = i & 31;
        float4 v = xg[i];
        __half2 h0 = __floats2half2_rn(v.x, v.y);
        __half2 h1 = __floats2half2_rn(v.z, v.w);
        uint2 st; st.x = *(unsigned*)&h0; st.y = *(unsigned*)&h1;
        *(uint2*)&xsh[r*136 + c4*4] = st;
    }
    for (int i = tid; i < 64*64; i += 256) {
        int r = i >> 6, c2 = i & 63;
        const float* wr = w + (size_t)(n0 + r)*129 + c2*2;
        __half2 h = __floats2half2_rn(wr[0], wr[1]);
        *(unsigned*)&wsh[r*136 + c2*2] = *(unsigned*)&h;
    }
    if (tid < 64) bsh[tid] = w[(size_t)(n0 + tid)*129 + 128];
    __syncthreads();

    float oacc[4][4];
#pragma unroll
    for (int nt = 0; nt < 4; nt++)
#pragma unroll
        for (int c = 0; c < 4; c++) oacc[nt][c] = 0.f;

#pragma unroll
    for (int kk = 0; kk < 8; kk++) {
        unsigned af[4];
        const int ar = (mt*16 + g)*136 + kk*16 + tg*2;
        af[0] = *(const unsigned*)&xsh[ar];
        af[1] = *(const unsigned*)&xsh[ar + 8*136];
        af[2] = *(const unsigned*)&xsh[ar + 8];
        af[3] = *(const unsigned*)&xsh[ar + 8*136 + 8];
#pragma unroll
        for (int nt = 0; nt < 4; nt++) {
            const int br = (ng*32 + nt*8 + g)*136 + kk*16 + tg*2;
            unsigned bf[2];
            bf[0] = *(const unsigned*)&wsh[br];
            bf[1] = *(const unsigned*)&wsh[br + 8];
            mma16816_(oacc[nt], af, bf);
        }
    }

#pragma unroll
    for (int nt = 0; nt < 4; nt++) {
        const int col = ng*32 + nt*8 + tg*2;
        oacc[nt][0] += bsh[col];     oacc[nt][1] += bsh[col + 1];
        oacc[nt][2] += bsh[col];     oacc[nt][3] += bsh[col + 1];
    }

    const int bi = m0 >> 9, tb = m0 & 511;
    const int cbase = n0 & 255;
    const int hh = n0 >> 8;

    if (cbase < 128) {
        __half* qg_ = g_qh + ((size_t)(bi*HH + hh)*TT + tb)*DD + cbase;
#pragma unroll
        for (int nt = 0; nt < 4; nt++) {
            const int col = ng*32 + nt*8 + tg*2;
            const int r0 = mt*16 + g;
            __half2 h01 = __floats2half2_rn(oacc[nt][0], oacc[nt][1]);
            __half2 h23 = __floats2half2_rn(oacc[nt][2], oacc[nt][3]);
            *(unsigned*)&qg_[(size_t)r0*DD + col]       = *(unsigned*)&h01;
            *(unsigned*)&qg_[(size_t)(r0 + 8)*DD + col] = *(unsigned*)&h23;
        }
    } else {
        __syncthreads();
        __half* vsm = xsh;             // 64 d-rows x 72 (t stride)
#pragma unroll
        for (int nt = 0; nt < 4; nt++) {
            const int dl = ng*32 + nt*8 + tg*2;
            const int r0 = mt*16 + g;
            vsm[dl*72 + r0]           = __float2half(oacc[nt][0]);
            vsm[(dl + 1)*72 + r0]     = __float2half(oacc[nt][1]);
            vsm[dl*72 + r0 + 8]       = __float2half(oacc[nt][2]);
            vsm[(dl + 1)*72 + r0 + 8] = __float2half(oacc[nt][3]);
        }
        __syncthreads();
        __half* vg = g_vT + ((size_t)(bi*HH + hh)*DD + (cbase - 128))*TT + tb;
        for (int i = tid; i < 1024; i += 256) {
            int row = i >> 4, seg = i & 15;
            uint2 val = *(uint2*)&vsm[row*72 + seg*4];
            *(uint2*)&vg[(size_t)row*TT + seg*4] = val;
        }
    }
}

// ---------------------------------------------------------------------------
// Kernel 1b: k8[b][h][s][d] = int8( x[b][s][d] * wk[h][d] * QINV )
// ---------------------------------------------------------------------------
__global__ __launch_bounds__(256) void k_kernel(const float* __restrict__ x,
                                                const float* __restrict__ wk) {
    __shared__ float xs[16*128];
    __shared__ float wks[8*128];

    const int b = blockIdx.y, s0 = blockIdx.x * 16;
    const int tid = threadIdx.x;

    const float4* xg = (const float4*)(x + ((size_t)b*TT + s0)*DD);
    for (int i = tid; i < 16*32; i += 256) ((float4*)xs)[i] = xg[i];
    for (int i = tid; i < 8*32; i += 256)  ((float4*)wks)[i] = ((const float4*)wk)[i];
    __syncthreads();

    for (int i = tid; i < 16*8*32; i += 256) {
        int d4 = i & 31, hh = (i >> 5) & 7, sl = i >> 8;
        float4 xv = *(const float4*)&xs[sl*128 + d4*4];
        float4 wv = *(const float4*)&wks[hh*128 + d4*4];
        unsigned p = pack4i_(q1_(xv.x*wv.x), q1_(xv.y*wv.y),
                             q1_(xv.z*wv.z), q1_(xv.w*wv.w));
        *(unsigned*)&g_k8[((size_t)(b*HH + hh)*TT + s0 + sl)*DD + d4*4] = p;
    }
}

// ---------------------------------------------------------------------------
// Kernel 2: fused L1 attention. int8 SAD (vabsdiff4.add) distance + HMMA P@V.
// smem (bytes):
//   [0,66560)        Ssh fp16 64 x 520
//   [66560,75776)    q8 64 x 144 int8    | phase3 vTsh fp16 128x136 overlays
//   [75776,84992)    k8 64 x 144 int8    |   [66560,101376)
// ---------------------------------------------------------------------------
#define SSTRIDE 520
#define OFF_Q8 66560
#define OFF_K8 75776
#define OFF_VT 66560
#define ATTN_SMEM 101376

__global__ __launch_bounds__(256) void attn_kernel(const float* __restrict__ msk) {
    extern __shared__ char smc[];
    __half* Ssh = (__half*)smc;
    char*   q8  = smc + OFF_Q8;   // stride 144
    char*   k8  = smc + OFF_K8;   // stride 144

    const int b  = blockIdx.z, h = blockIdx.y;
    const int t0 = blockIdx.x * 64;
    const int tid = threadIdx.x;
    const int tx  = tid & 15, ty = tid >> 4;

    const uint4* khg8 = (const uint4*)(g_k8 + ((size_t)(b*HH + h))*TT*DD);

    // stage q tile: fp16 -> int8 quantize (one-time)
    const uint4* qg = (const uint4*)(g_qh + (((size_t)(b*HH + h))*TT + t0)*DD);
#pragma unroll
    for (int u = 0; u < 2; u++) {
        int idx = tid + u*256;              // 0..511
        int r = idx >> 3, seg = idx & 7;    // 16 int8 per seg
        uint4 ha = qg[r*16 + seg*2];
        uint4 hb = qg[r*16 + seg*2 + 1];
        float2 f0 = __half22float2(*(__half2*)&ha.x);
        float2 f1 = __half22float2(*(__half2*)&ha.y);
        float2 f2 = __half22float2(*(__half2*)&ha.z);
        float2 f3 = __half22float2(*(__half2*)&ha.w);
        float2 f4 = __half22float2(*(__half2*)&hb.x);
        float2 f5 = __half22float2(*(__half2*)&hb.y);
        float2 f6 = __half22float2(*(__half2*)&hb.z);
        float2 f7 = __half22float2(*(__half2*)&hb.w);
        uint4 o;
        o.x = pack4i_(q1_(f0.x), q1_(f0.y), q1_(f1.x), q1_(f1.y));
        o.y = pack4i_(q1_(f2.x), q1_(f2.y), q1_(f3.x), q1_(f3.y));
        o.z = pack4i_(q1_(f4.x), q1_(f4.y), q1_(f5.x), q1_(f5.y));
        o.w = pack4i_(q1_(f6.x), q1_(f6.y), q1_(f7.x), q1_(f7.y));
        *(uint4*)&q8[r*144 + seg*16] = o;
    }

    // prefetch k tile 0 (int8: 512 uint4 per tile, 2 per thread)
    uint4 kreg[2];
#pragma unroll
    for (int u = 0; u < 2; u++) kreg[u] = khg8[tid + u*256];

    // ---------------- Phase 1: score tiles (SAD) ----------------
    for (int sc = 0; sc < 8; sc++) {
        const int s0 = sc * 64;
#pragma unroll
        for (int u = 0; u < 2; u++) {
            int idx = tid + u*256;
            int r = idx >> 3, seg = idx & 7;
            *(uint4*)&k8[r*144 + seg*16] = kreg[u];
        }
        __syncthreads();

        if (sc + 1 < 8) {
#pragma unroll
            for (int u = 0; u < 2; u++) kreg[u] = khg8[(sc + 1)*512 + tid + u*256];
        }

        unsigned acc[4][4];
#pragma unroll
        for (int i = 0; i < 4; i++)
#pragma unroll
            for (int j = 0; j < 4; j++) acc[i][j] = 0u;

#pragma unroll
        for (int ch = 0; ch < 8; ch++) {
            uint4 qv[4], kv[4];
#pragma unroll
            for (int i = 0; i < 4; i++) qv[i] = *(const uint4*)&q8[(ty*4 + i)*144 + ch*16];
#pragma unroll
            for (int j = 0; j < 4; j++) kv[j] = *(const uint4*)&k8[(tx + 16*j)*144 + ch*16];
#pragma unroll
            for (int i = 0; i < 4; i++)
#pragma unroll
                for (int j = 0; j < 4; j++) {
                    unsigned a = acc[i][j];
                    a = vad4_(qv[i].x, kv[j].x, a);
                    a = vad4_(qv[i].y, kv[j].y, a);
                    a = vad4_(qv[i].z, kv[j].z, a);
                    a = vad4_(qv[i].w, kv[j].w, a);
                    acc[i][j] = a;
                }
        }

#pragma unroll
        for (int i = 0; i < 4; i++)
#pragma unroll
            for (int j = 0; j < 4; j++)
                Ssh[(ty*4 + i)*SSTRIDE + s0 + tx + 16*j] =
                    __float2half((float)acc[i][j] * CNEG);
        __syncthreads();
    }

    // ---------------- Phase 2: row softmax + mask (fp32 in registers) ------
    const int warp = tid >> 5, lane = tid & 31;
    for (int r = warp; r < 64; r += 8) {
        __half* row = Ssh + r*SSTRIDE;
        float vals[16];
        float m = -1e30f;
#pragma unroll
        for (int i = 0; i < 16; i++) {
            vals[i] = __half2float(row[lane + i*32]);
            m = fmaxf(m, vals[i]);
        }
#pragma unroll
        for (int o = 16; o > 0; o >>= 1) m = fmaxf(m, __shfl_xor_sync(0xffffffffu, m, o));
        float sum = 0.f;
#pragma unroll
        for (int i = 0; i < 16; i++) { vals[i] = __expf(vals[i] - m); sum += vals[i]; }
#pragma unroll
        for (int o = 16; o > 0; o >>= 1) sum += __shfl_xor_sync(0xffffffffu, sum, o);
        float inv = 1.f / sum;
        const float* mrow = msk + ((size_t)(h*TT + t0 + r))*TT;
#pragma unroll
        for (int i = 0; i < 16; i++)
            row[lane + i*32] = __float2half(vals[i] * inv * mrow[lane + i*32]);
    }
    __syncthreads();

    // ---------------- Phase 3: O = P @ V via mma.sync (A = fp16 S direct) --
    __half* vTsh = (__half*)(smc + OFF_VT);
    const __half* vTg = g_vT + ((size_t)(b*HH + h))*DD*TT;
    const int mt = warp & 3, ng = warp >> 2;
    const int g = lane >> 2, tg = lane & 3;

    float oacc[8][4];
#pragma unroll
    for (int nt = 0; nt < 8; nt++)
#pragma unroll
        for (int c = 0; c < 4; c++) oacc[nt][c] = 0.f;

    for (int sc = 0; sc < 4; sc++) {
        const int s0 = sc * 128;
        for (int i = tid; i < 2048; i += 256) {
            int r = i >> 4, kg = i & 15;
            uint4 val = *(const uint4*)(vTg + (size_t)r*TT + s0 + kg*8);
            *(uint4*)&vTsh[r*136 + kg*8] = val;
        }
        __syncthreads();

#pragma unroll
        for (int kk = 0; kk < 8; kk++) {
            const int ar = (mt*16 + g)*SSTRIDE + s0 + kk*16 + tg*2;
            unsigned af[4];
            af[0] = *(const unsigned*)&Ssh[ar];
            af[1] = *(const unsigned*)&Ssh[ar + 8*SSTRIDE];
            af[2] = *(const unsigned*)&Ssh[ar + 8];
            af[3] = *(const unsigned*)&Ssh[ar + 8*SSTRIDE + 8];

            const int kb = kk*16 + tg*2;
#pragma unroll
            for (int nt = 0; nt < 8; nt++) {
                int row = ng*64 + nt*8 + g;
                unsigned bf[2];
                bf[0] = *(const unsigned*)&vTsh[row*136 + kb];
                bf[1] = *(const unsigned*)&vTsh[row*136 + kb + 8];
                mma16816_(oacc[nt], af, bf);
            }
        }
        __syncthreads();
    }

    float* og = g_o + (((size_t)(b*HH + h))*TT + t0)*DD;
#pragma unroll
    for (int nt = 0; nt < 8; nt++) {
        int d = ng*64 + nt*8 + tg*2;
        int r0 = mt*16 + g;
        *(float2*)&og[(size_t)r0*DD + d]       = make_float2(oacc[nt][0], oacc[nt][1]);
        *(float2*)&og[(size_t)(r0 + 8)*DD + d] = make_float2(oacc[nt][2], oacc[nt][3]);
    }
}

// ---------------------------------------------------------------------------
// Kernel 3: head-reduce + quickGELU + fanout HMMA + residual (unchanged)
// ---------------------------------------------------------------------------
#define FIN_SMEM (128*136*2 + 16*136*2 + 512)

__global__ __launch_bounds__(256) void final_kernel(const float* __restrict__ x,
                                                    const float* __restrict__ fw,
                                                    float* __restrict__ out) {
    extern __shared__ char fsm[];
    __half* Wh   = (__half*)fsm;                      // 128 x 136
    __half* yosh = (__half*)(fsm + 128*136*2);        // 16 x 136
    float*  bsh  = (float*)(fsm + 128*136*2 + 16*136*2);

    const int b = blockIdx.y, t0 = blockIdx.x * 16;
    const int tid = threadIdx.x;
    const int warp = tid >> 5, lane = tid & 31;
    const int g = lane >> 2, tg = lane & 3;

    for (int i = tid; i < 128*64; i += 256) {
        int r = i >> 6, c2 = i & 63;
        const float* wr = fw + (size_t)r*129 + c2*2;
        __half2 h = __floats2half2_rn(wr[0], wr[1]);
        *(unsigned*)&Wh[r*136 + c2*2] = *(unsigned*)&h;
    }
    if (tid < 128) bsh[tid] = fw[(size_t)tid*129 + 128];

    for (int i = tid; i < 16*128; i += 256) {
        int r = i >> 7, dd = i & 127;
        float bo = 0.f;
#pragma unroll
        for (int h = 0; h < HH; h++)
            bo += g_o[(((size_t)(b*HH + h))*TT + t0 + r)*DD + dd];
        float z  = bo + 4.5f;
        float sg = 1.f / (1.f + __expf(-1.702f * z));
        yosh[r*136 + dd] = __float2half(z*sg - 4.5f);
    }
    __syncthreads();

    float acc[2][4];
#pragma unroll
    for (int nt = 0; nt < 2; nt++)
#pragma unroll
        for (int c = 0; c < 4; c++) acc[nt][c] = 0.f;

#pragma unroll
    for (int kk = 0; kk < 8; kk++) {
        unsigned af[4];
        const int ar = g*136 + kk*16 + tg*2;
        af[0] = *(const unsigned*)&yosh[ar];
        af[1] = *(const unsigned*)&yosh[ar + 8*136];
        af[2] = *(const unsigned*)&yosh[ar + 8];
        af[3] = *(const unsigned*)&yosh[ar + 8*136 + 8];
#pragma unroll
        for (int nt = 0; nt < 2; nt++) {
            const int br = (warp*16 + nt*8 + g)*136 + kk*16 + tg*2;
            unsigned bf[2];
            bf[0] = *(const unsigned*)&Wh[br];
            bf[1] = *(const unsigned*)&Wh[br + 8];
            mma16816_(acc[nt], af, bf);
        }
    }

#pragma unroll
    for (int nt = 0; nt < 2; nt++) {
        const int col = warp*16 + nt*8 + tg*2;
        const float b0 = bsh[col], b1 = bsh[col + 1];
        size_t i0 = ((size_t)b*TT + t0 + g)*DD + col;
        size_t i1 = ((size_t)b*TT + t0 + g + 8)*DD + col;
        out[i0]     = x[i0]     + acc[nt][0] + b0;
        out[i0 + 1] = x[i0 + 1] + acc[nt][1] + b1;
        out[i1]     = x[i1]     + acc[nt][2] + b0;
        out[i1 + 1] = x[i1 + 1] + acc[nt][3] + b1;
    }
}

// ---------------------------------------------------------------------------
extern "C" void kernel_launch(void* const* d_in, const int* in_sizes, int n_in,
                              void* d_out, int out_size) {
    const float* x   = (const float*)d_in[0];
    const float* msk = (const float*)d_in[1];
    const float* wqv = (const float*)d_in[2];
    const float* wk  = (const float*)d_in[3];
    const float* fw  = (const float*)d_in[4];
    float* out = (float*)d_out;

    cudaFuncSetAttribute(qv_kernel,    cudaFuncAttributeMaxDynamicSharedMemorySize,
                         QV_SMEM);
    cudaFuncSetAttribute(attn_kernel,  cudaFuncAttributeMaxDynamicSharedMemorySize,
                         ATTN_SMEM);
    cudaFuncSetAttribute(final_kernel, cudaFuncAttributeMaxDynamicSharedMemorySize,
                         FIN_SMEM);

    qv_kernel<<<dim3(32, 64), 256, QV_SMEM>>>(x, wqv);
    k_kernel<<<dim3(TT/16, BB), 256>>>(x, wk);
    attn_kernel<<<dim3(TT/64, HH, BB), 256, ATTN_SMEM>>>(msk);
    final_kernel<<<dim3(TT/16, BB), 256, FIN_SMEM>>>(x, fw, out);
}

// round 15
// speedup vs baseline: 2.3012x; 1.0321x over previous
#include <cuda_runtime.h>
#include <cuda_fp16.h>
#include <math.h>
#include <cstdint>

#define BB 8
#define TT 512
#define DD 128
#define HH 8

// int8 quantization scale for q/k distance path
#define QINV  80.0f
// logit constant: -(1/QINV)/sqrt(128)
#define CNEG  (-0.0011048543f)

typedef unsigned long long u64;

// m16n8k16 f16 MMA, fp32 accumulate (portable PTX, runs on sm_103 HMMA)
__device__ __forceinline__ void mma16816_(float* c, const unsigned* a, const unsigned* b) {
    asm volatile(
        "mma.sync.aligned.m16n8k16.row.col.f32.f16.f16.f32 "
        "{%0,%1,%2,%3}, {%4,%5,%6,%7}, {%8,%9}, {%0,%1,%2,%3};"
        : "+f"(c[0]), "+f"(c[1]), "+f"(c[2]), "+f"(c[3])
        : "r"(a[0]), "r"(a[1]), "r"(a[2]), "r"(a[3]), "r"(b[0]), "r"(b[1]));
}

// SAD: d = c + sum_i |sbyte_i(a) - sbyte_i(b)|  (single HW instruction)
__device__ __forceinline__ unsigned vad4_(unsigned a, unsigned b, unsigned c) {
    unsigned d;
    asm("vabsdiff4.u32.s32.s32.add %0, %1, %2, %3;" : "=r"(d) : "r"(a), "r"(b), "r"(c));
    return d;
}

__device__ __forceinline__ int q1_(float f) {
    int i = __float2int_rn(f * QINV);
    return max(-127, min(127, i));
}
__device__ __forceinline__ unsigned pack4i_(int a, int b, int c, int d) {
    return (unsigned)(a & 255) | ((unsigned)(b & 255) << 8) |
           ((unsigned)(c & 255) << 16) | ((unsigned)(d & 255) << 24);
}

// Scratch
__device__ __half g_qh[(size_t)BB*HH*TT*DD];               // q[b][h][t][d] fp16
__device__ __align__(16) signed char g_k8[(size_t)BB*HH*TT*DD]; // k int8 (x*wk, scale 1/QINV)
__device__ __half g_vT[(size_t)BB*HH*DD*TT];               // vT[b][h][d][s] fp16
__device__ __half g_oh[(size_t)BB*HH*TT*DD];               // o[b][h][t][d] fp16

// ---------------------------------------------------------------------------
// Kernel 1: QV projection via mma.sync. 128(m) x 64(n) tiles (halved W traffic).
// Warp w handles m-rows [w*16, w*16+16), all 64 n-cols (8 n-tiles m16n8).
// ---------------------------------------------------------------------------
#define QV_SMEM (128*136*2 + 64*136*2)   // xsh + wsh

__global__ __launch_bounds__(256) void qv_kernel(const float* __restrict__ x,
                                                 const float* __restrict__ w) {
    extern __shared__ __half smh[];
    __half* xsh = smh;             // 128 x 136
    __half* wsh = smh + 128*136;   // 64 x 136
    __shared__ float bsh[64];

    const int tid = threadIdx.x;
    const int warp = tid >> 5, lane = tid & 31;
    const int g = lane >> 2, tg = lane & 3;
    const int m0 = blockIdx.y * 128;   // bt tile (within one b: 512%128==0)
    const int n0 = blockIdx.x * 64;    // o tile

    const float4* xg = (const float4*)(x + (size_t)m0*DD);
    for (int i = tid; i < 128*32; i += 256) {
        int r = i >> 5, c4 = i & 31;
        float4 v = xg[i];
        __half2 h0 = __floats2half2_rn(v.x, v.y);
        __half2 h1 = __floats2half2_rn(v.z, v.w);
        uint2 st; st.x = *(unsigned*)&h0; st.y = *(unsigned*)&h1;
        *(uint2*)&xsh[r*136 + c4*4] = st;
    }
    for (int i = tid; i < 64*64; i += 256) {
        int r = i >> 6, c2 = i & 63;
        const float* wr = w + (size_t)(n0 + r)*129 + c2*2;
        __half2 h = __floats2half2_rn(wr[0], wr[1]);
        *(unsigned*)&wsh[r*136 + c2*2] = *(unsigned*)&h;
    }
    if (tid < 64) bsh[tid] = w[(size_t)(n0 + tid)*129 + 128];
    __syncthreads();

    float acc[8][4];
#pragma unroll
    for (int nt = 0; nt < 8; nt++)
#pragma unroll
        for (int c = 0; c < 4; c++) acc[nt][c] = 0.f;

#pragma unroll
    for (int kk = 0; kk < 8; kk++) {
        unsigned af[4];
        const int ar = (warp*16 + g)*136 + kk*16 + tg*2;
        af[0] = *(const unsigned*)&xsh[ar];
        af[1] = *(const unsigned*)&xsh[ar + 8*136];
        af[2] = *(const unsigned*)&xsh[ar + 8];
        af[3] = *(const unsigned*)&xsh[ar + 8*136 + 8];
#pragma unroll
        for (int nt = 0; nt < 8; nt++) {
            const int br = (nt*8 + g)*136 + kk*16 + tg*2;
            unsigned bf[2];
            bf[0] = *(const unsigned*)&wsh[br];
            bf[1] = *(const unsigned*)&wsh[br + 8];
            mma16816_(acc[nt], af, bf);
        }
    }

#pragma unroll
    for (int nt = 0; nt < 8; nt++) {
        const int col = nt*8 + tg*2;
        acc[nt][0] += bsh[col];     acc[nt][1] += bsh[col + 1];
        acc[nt][2] += bsh[col];     acc[nt][3] += bsh[col + 1];
    }

    const int bi = m0 >> 9, tb = m0 & 511;
    const int cbase = n0 & 255;     // uniform per CTA: 0,64 -> q ; 128,192 -> v
    const int hh = n0 >> 8;

    if (cbase < 128) {
        __half* qg_ = g_qh + ((size_t)(bi*HH + hh)*TT + tb)*DD + cbase;
#pragma unroll
        for (int nt = 0; nt < 8; nt++) {
            const int col = nt*8 + tg*2;
            const int r0 = warp*16 + g;
            __half2 h01 = __floats2half2_rn(acc[nt][0], acc[nt][1]);
            __half2 h23 = __floats2half2_rn(acc[nt][2], acc[nt][3]);
            *(unsigned*)&qg_[(size_t)r0*DD + col]       = *(unsigned*)&h01;
            *(unsigned*)&qg_[(size_t)(r0 + 8)*DD + col] = *(unsigned*)&h23;
        }
    } else {
        // v tile: transpose through smem (64 d-rows x 128 t, stride 144 halves)
        __syncthreads();
        __half* vsm = xsh;
#pragma unroll
        for (int nt = 0; nt < 8; nt++) {
            const int dl = nt*8 + tg*2;
            const int r0 = warp*16 + g;
            vsm[dl*144 + r0]           = __float2half(acc[nt][0]);
            vsm[(dl + 1)*144 + r0]     = __float2half(acc[nt][1]);
            vsm[dl*144 + r0 + 8]       = __float2half(acc[nt][2]);
            vsm[(dl + 1)*144 + r0 + 8] = __float2half(acc[nt][3]);
        }
        __syncthreads();
        __half* vg = g_vT + ((size_t)(bi*HH + hh)*DD + (cbase - 128))*TT + tb;
        for (int i = tid; i < 64*16; i += 256) {
            int row = i >> 4, seg = i & 15;
            uint4 val = *(uint4*)&vsm[row*144 + seg*8];
            *(uint4*)&vg[(size_t)row*TT + seg*8] = val;
        }
    }
}

// ---------------------------------------------------------------------------
// Kernel 1b: k8[b][h][s][d] = int8( x[b][s][d] * wk[h][d] * QINV )
// ---------------------------------------------------------------------------
__global__ __launch_bounds__(256) void k_kernel(const float* __restrict__ x,
                                                const float* __restrict__ wk) {
    __shared__ float xs[16*128];
    __shared__ float wks[8*128];

    const int b = blockIdx.y, s0 = blockIdx.x * 16;
    const int tid = threadIdx.x;

    const float4* xg = (const float4*)(x + ((size_t)b*TT + s0)*DD);
    for (int i = tid; i < 16*32; i += 256) ((float4*)xs)[i] = xg[i];
    for (int i = tid; i < 8*32; i += 256)  ((float4*)wks)[i] = ((const float4*)wk)[i];
    __syncthreads();

    for (int i = tid; i < 16*8*32; i += 256) {
        int d4 = i & 31, hh = (i >> 5) & 7, sl = i >> 8;
        float4 xv = *(const float4*)&xs[sl*128 + d4*4];
        float4 wv = *(const float4*)&wks[hh*128 + d4*4];
        unsigned p = pack4i_(q1_(xv.x*wv.x), q1_(xv.y*wv.y),
                             q1_(xv.z*wv.z), q1_(xv.w*wv.w));
        *(unsigned*)&g_k8[((size_t)(b*HH + hh)*TT + s0 + sl)*DD + d4*4] = p;
    }
}

// ---------------------------------------------------------------------------
// Kernel 2: fused L1 attention. int8 SAD distance + HMMA P@V; o stored fp16.
// ---------------------------------------------------------------------------
#define SSTRIDE 520
#define OFF_Q8 66560
#define OFF_K8 75776
#define OFF_VT 66560
#define ATTN_SMEM 101376

__global__ __launch_bounds__(256) void attn_kernel(const float* __restrict__ msk) {
    extern __shared__ char smc[];
    __half* Ssh = (__half*)smc;
    char*   q8  = smc + OFF_Q8;   // stride 144
    char*   k8  = smc + OFF_K8;   // stride 144

    const int b  = blockIdx.z, h = blockIdx.y;
    const int t0 = blockIdx.x * 64;
    const int tid = threadIdx.x;
    const int tx  = tid & 15, ty = tid >> 4;

    const uint4* khg8 = (const uint4*)(g_k8 + ((size_t)(b*HH + h))*TT*DD);

    // stage q tile: fp16 -> int8 quantize (one-time)
    const uint4* qg = (const uint4*)(g_qh + (((size_t)(b*HH + h))*TT + t0)*DD);
#pragma unroll
    for (int u = 0; u < 2; u++) {
        int idx = tid + u*256;              // 0..511
        int r = idx >> 3, seg = idx & 7;    // 16 int8 per seg
        uint4 ha = qg[r*16 + seg*2];
        uint4 hb = qg[r*16 + seg*2 + 1];
        float2 f0 = __half22float2(*(__half2*)&ha.x);
        float2 f1 = __half22float2(*(__half2*)&ha.y);
        float2 f2 = __half22float2(*(__half2*)&ha.z);
        float2 f3 = __half22float2(*(__half2*)&ha.w);
        float2 f4 = __half22float2(*(__half2*)&hb.x);
        float2 f5 = __half22float2(*(__half2*)&hb.y);
        float2 f6 = __half22float2(*(__half2*)&hb.z);
        float2 f7 = __half22float2(*(__half2*)&hb.w);
        uint4 o;
        o.x = pack4i_(q1_(f0.x), q1_(f0.y), q1_(f1.x), q1_(f1.y));
        o.y = pack4i_(q1_(f2.x), q1_(f2.y), q1_(f3.x), q1_(f3.y));
        o.z = pack4i_(q1_(f4.x), q1_(f4.y), q1_(f5.x), q1_(f5.y));
        o.w = pack4i_(q1_(f6.x), q1_(f6.y), q1_(f7.x), q1_(f7.y));
        *(uint4*)&q8[r*144 + seg*16] = o;
    }

    // prefetch k tile 0 (int8: 512 uint4 per tile, 2 per thread)
    uint4 kreg[2];
#pragma unroll
    for (int u = 0; u < 2; u++) kreg[u] = khg8[tid + u*256];

    // ---------------- Phase 1: score tiles (SAD) ----------------
    for (int sc = 0; sc < 8; sc++) {
        const int s0 = sc * 64;
#pragma unroll
        for (int u = 0; u < 2; u++) {
            int idx = tid + u*256;
            int r = idx >> 3, seg = idx & 7;
            *(uint4*)&k8[r*144 + seg*16] = kreg[u];
        }
        __syncthreads();

        if (sc + 1 < 8) {
#pragma unroll
            for (int u = 0; u < 2; u++) kreg[u] = khg8[(sc + 1)*512 + tid + u*256];
        }

        unsigned acc[4][4];
#pragma unroll
        for (int i = 0; i < 4; i++)
#pragma unroll
            for (int j = 0; j < 4; j++) acc[i][j] = 0u;

#pragma unroll
        for (int ch = 0; ch < 8; ch++) {
            uint4 qv[4], kv[4];
#pragma unroll
            for (int i = 0; i < 4; i++) qv[i] = *(const uint4*)&q8[(ty*4 + i)*144 + ch*16];
#pragma unroll
            for (int j = 0; j < 4; j++) kv[j] = *(const uint4*)&k8[(tx + 16*j)*144 + ch*16];
#pragma unroll
            for (int i = 0; i < 4; i++)
#pragma unroll
                for (int j = 0; j < 4; j++) {
                    unsigned a = acc[i][j];
                    a = vad4_(qv[i].x, kv[j].x, a);
                    a = vad4_(qv[i].y, kv[j].y, a);
                    a = vad4_(qv[i].z, kv[j].z, a);
                    a = vad4_(qv[i].w, kv[j].w, a);
                    acc[i][j] = a;
                }
        }

#pragma unroll
        for (int i = 0; i < 4; i++)
#pragma unroll
            for (int j = 0; j < 4; j++)
                Ssh[(ty*4 + i)*SSTRIDE + s0 + tx + 16*j] =
                    __float2half((float)acc[i][j] * CNEG);
        __syncthreads();
    }

    // ---------------- Phase 2: row softmax + mask (fp32 in registers) ------
    const int warp = tid >> 5, lane = tid & 31;
    for (int r = warp; r < 64; r += 8) {
        __half* row = Ssh + r*SSTRIDE;
        float vals[16];
        float m = -1e30f;
#pragma unroll
        for (int i = 0; i < 16; i++) {
            vals[i] = __half2float(row[lane + i*32]);
            m = fmaxf(m, vals[i]);
        }
#pragma unroll
        for (int o = 16; o > 0; o >>= 1) m = fmaxf(m, __shfl_xor_sync(0xffffffffu, m, o));
        float sum = 0.f;
#pragma unroll
        for (int i = 0; i < 16; i++) { vals[i] = __expf(vals[i] - m); sum += vals[i]; }
#pragma unroll
        for (int o = 16; o > 0; o >>= 1) sum += __shfl_xor_sync(0xffffffffu, sum, o);
        float inv = 1.f / sum;
        const float* mrow = msk + ((size_t)(h*TT + t0 + r))*TT;
#pragma unroll
        for (int i = 0; i < 16; i++)
            row[lane + i*32] = __float2half(vals[i] * inv * mrow[lane + i*32]);
    }
    __syncthreads();

    // ---------------- Phase 3: O = P @ V via mma.sync ----------------
    __half* vTsh = (__half*)(smc + OFF_VT);
    const __half* vTg = g_vT + ((size_t)(b*HH + h))*DD*TT;
    const int mt = warp & 3, ng = warp >> 2;
    const int g = lane >> 2, tg = lane & 3;

    float oacc[8][4];
#pragma unroll
    for (int nt = 0; nt < 8; nt++)
#pragma unroll
        for (int c = 0; c < 4; c++) oacc[nt][c] = 0.f;

    for (int sc = 0; sc < 4; sc++) {
        const int s0 = sc * 128;
        for (int i = tid; i < 2048; i += 256) {
            int r = i >> 4, kg = i & 15;
            uint4 val = *(const uint4*)(vTg + (size_t)r*TT + s0 + kg*8);
            *(uint4*)&vTsh[r*136 + kg*8] = val;
        }
        __syncthreads();

#pragma unroll
        for (int kk = 0; kk < 8; kk++) {
            const int ar = (mt*16 + g)*SSTRIDE + s0 + kk*16 + tg*2;
            unsigned af[4];
            af[0] = *(const unsigned*)&Ssh[ar];
            af[1] = *(const unsigned*)&Ssh[ar + 8*SSTRIDE];
            af[2] = *(const unsigned*)&Ssh[ar + 8];
            af[3] = *(const unsigned*)&Ssh[ar + 8*SSTRIDE + 8];

            const int kb = kk*16 + tg*2;
#pragma unroll
            for (int nt = 0; nt < 8; nt++) {
                int row = ng*64 + nt*8 + g;
                unsigned bf[2];
                bf[0] = *(const unsigned*)&vTsh[row*136 + kb];
                bf[1] = *(const unsigned*)&vTsh[row*136 + kb + 8];
                mma16816_(oacc[nt], af, bf);
            }
        }
        __syncthreads();
    }

    __half* og = g_oh + (((size_t)(b*HH + h))*TT + t0)*DD;
#pragma unroll
    for (int nt = 0; nt < 8; nt++) {
        int d = ng*64 + nt*8 + tg*2;
        int r0 = mt*16 + g;
        __half2 h01 = __floats2half2_rn(oacc[nt][0], oacc[nt][1]);
        __half2 h23 = __floats2half2_rn(oacc[nt][2], oacc[nt][3]);
        *(unsigned*)&og[(size_t)r0*DD + d]       = *(unsigned*)&h01;
        *(unsigned*)&og[(size_t)(r0 + 8)*DD + d] = *(unsigned*)&h23;
    }
}

// ---------------------------------------------------------------------------
// Kernel 3: head-reduce (fp16 o) + quickGELU + fanout HMMA + residual
// ---------------------------------------------------------------------------
#define FIN_SMEM (128*136*2 + 16*136*2 + 512)

__global__ __launch_bounds__(256) void final_kernel(const float* __restrict__ x,
                                                    const float* __restrict__ fw,
                                                    float* __restrict__ out) {
    extern __shared__ char fsm[];
    __half* Wh   = (__half*)fsm;                      // 128 x 136
    __half* yosh = (__half*)(fsm + 128*136*2);        // 16 x 136
    float*  bsh  = (float*)(fsm + 128*136*2 + 16*136*2);

    const int b = blockIdx.y, t0 = blockIdx.x * 16;
    const int tid = threadIdx.x;
    const int warp = tid >> 5, lane = tid & 31;
    const int g = lane >> 2, tg = lane & 3;

    for (int i = tid; i < 128*64; i += 256) {
        int r = i >> 6, c2 = i & 63;
        const float* wr = fw + (size_t)r*129 + c2*2;
        __half2 h = __floats2half2_rn(wr[0], wr[1]);
        *(unsigned*)&Wh[r*136 + c2*2] = *(unsigned*)&h;
    }
    if (tid < 128) bsh[tid] = fw[(size_t)tid*129 + 128];

    // h-reduce (fp16 pairs) + quickGELU -> yosh fp16
    for (int i = tid; i < 16*64; i += 256) {
        int r = i >> 6, d2 = i & 63;
        float2 bo = make_float2(0.f, 0.f);
#pragma unroll
        for (int h = 0; h < HH; h++) {
            __half2 v = *(const __half2*)&g_oh[(((size_t)(b*HH + h))*TT + t0 + r)*DD + d2*2];
            float2 f = __half22float2(v);
            bo.x += f.x; bo.y += f.y;
        }
        float z0 = bo.x + 4.5f, z1 = bo.y + 4.5f;
        float s0 = 1.f / (1.f + __expf(-1.702f * z0));
        float s1 = 1.f / (1.f + __expf(-1.702f * z1));
        __half2 hy = __floats2half2_rn(z0*s0 - 4.5f, z1*s1 - 4.5f);
        *(unsigned*)&yosh[r*136 + d2*2] = *(unsigned*)&hy;
    }
    __syncthreads();

    float acc[2][4];
#pragma unroll
    for (int nt = 0; nt < 2; nt++)
#pragma unroll
        for (int c = 0; c < 4; c++) acc[nt][c] = 0.f;

#pragma unroll
    for (int kk = 0; kk < 8; kk++) {
        unsigned af[4];
        const int ar = g*136 + kk*16 + tg*2;
        af[0] = *(const unsigned*)&yosh[ar];
        af[1] = *(const unsigned*)&yosh[ar + 8*136];
        af[2] = *(const unsigned*)&yosh[ar + 8];
        af[3] = *(const unsigned*)&yosh[ar + 8*136 + 8];
#pragma unroll
        for (int nt = 0; nt < 2; nt++) {
            const int br = (warp*16 + nt*8 + g)*136 + kk*16 + tg*2;
            unsigned bf[2];
            bf[0] = *(const unsigned*)&Wh[br];
            bf[1] = *(const unsigned*)&Wh[br + 8];
            mma16816_(acc[nt], af, bf);
        }
    }

#pragma unroll
    for (int nt = 0; nt < 2; nt++) {
        const int col = warp*16 + nt*8 + tg*2;
        const float b0 = bsh[col], b1 = bsh[col + 1];
        size_t i0 = ((size_t)b*TT + t0 + g)*DD + col;
        size_t i1 = ((size_t)b*TT + t0 + g + 8)*DD + col;
        out[i0]     = x[i0]     + acc[nt][0] + b0;
        out[i0 + 1] = x[i0 + 1] + acc[nt][1] + b1;
        out[i1]     = x[i1]     + acc[nt][2] + b0;
        out[i1 + 1] = x[i1 + 1] + acc[nt][3] + b1;
    }
}

// ---------------------------------------------------------------------------
extern "C" void kernel_launch(void* const* d_in, const int* in_sizes, int n_in,
                              void* d_out, int out_size) {
    const float* x   = (const float*)d_in[0];
    const float* msk = (const float*)d_in[1];
    const float* wqv = (const float*)d_in[2];
    const float* wk  = (const float*)d_in[3];
    const float* fw  = (const float*)d_in[4];
    float* out = (float*)d_out;

    cudaFuncSetAttribute(qv_kernel,    cudaFuncAttributeMaxDynamicSharedMemorySize,
                         QV_SMEM);
    cudaFuncSetAttribute(attn_kernel,  cudaFuncAttributeMaxDynamicSharedMemorySize,
                         ATTN_SMEM);
    cudaFuncSetAttribute(final_kernel, cudaFuncAttributeMaxDynamicSharedMemorySize,
                         FIN_SMEM);

    qv_kernel<<<dim3(32, 32), 256, QV_SMEM>>>(x, wqv);
    k_kernel<<<dim3(TT/16, BB), 256>>>(x, wk);
    attn_kernel<<<dim3(TT/64, HH, BB), 256, ATTN_SMEM>>>(msk);
    final_kernel<<<dim3(TT/16, BB), 256, FIN_SMEM>>>(x, fw, out);
}

// round 16
// speedup vs baseline: 2.3962x; 1.0413x over previous
#include <cuda_runtime.h>
#include <cuda_fp16.h>
#include <math.h>
#include <cstdint>

#define BB 8
#define TT 512
#define DD 128
#define HH 8

#define QINV  80.0f
#define CNEG  (-0.0011048543f)

typedef unsigned long long u64;

__device__ __forceinline__ void mma16816_(float* c, const unsigned* a, const unsigned* b) {
    asm volatile(
        "mma.sync.aligned.m16n8k16.row.col.f32.f16.f16.f32 "
        "{%0,%1,%2,%3}, {%4,%5,%6,%7}, {%8,%9}, {%0,%1,%2,%3};"
        : "+f"(c[0]), "+f"(c[1]), "+f"(c[2]), "+f"(c[3])
        : "r"(a[0]), "r"(a[1]), "r"(a[2]), "r"(a[3]), "r"(b[0]), "r"(b[1]));
}

__device__ __forceinline__ unsigned vad4_(unsigned a, unsigned b, unsigned c) {
    unsigned d;
    asm("vabsdiff4.u32.s32.s32.add %0, %1, %2, %3;" : "=r"(d) : "r"(a), "r"(b), "r"(c));
    return d;
}

__device__ __forceinline__ int q1_(float f) {
    int i = __float2int_rn(f * QINV);
    return max(-127, min(127, i));
}
__device__ __forceinline__ unsigned pack4i_(int a, int b, int c, int d) {
    return (unsigned)(a & 255) | ((unsigned)(b & 255) << 8) |
           ((unsigned)(c & 255) << 16) | ((unsigned)(d & 255) << 24);
}

__device__ __half g_qh[(size_t)BB*HH*TT*DD];
__device__ __align__(16) signed char g_k8[(size_t)BB*HH*TT*DD];
__device__ __half g_vT[(size_t)BB*HH*DD*TT];
__device__ __half g_oh[(size_t)BB*HH*TT*DD];

// ---------------------------------------------------------------------------
#define QV_SMEM (128*136*2 + 64*136*2)

__global__ __launch_bounds__(256) void qv_kernel(const float* __restrict__ x,
                                                 const float* __restrict__ w) {
    extern __shared__ __half smh[];
    __half* xsh = smh;             // 128 x 136
    __half* wsh = smh + 128*136;   // 64 x 136
    __shared__ float bsh[64];

    const int tid = threadIdx.x;
    const int warp = tid >> 5, lane = tid & 31;
    const int g = lane >> 2, tg = lane & 3;
    const int m0 = blockIdx.y * 128;
    const int n0 = blockIdx.x * 64;

    const float4* xg = (const float4*)(x + (size_t)m0*DD);
    for (int i = tid; i < 128*32; i += 256) {
        int r = i >> 5, c4 = i & 31;
        float4 v = xg[i];
        __half2 h0 = __floats2half2_rn(v.x, v.y);
        __half2 h1 = __floats2half2_rn(v.z, v.w);
        uint2 st; st.x = *(unsigned*)&h0; st.y = *(unsigned*)&h1;
        *(uint2*)&xsh[r*136 + c4*4] = st;
    }
    for (int i = tid; i < 64*64; i += 256) {
        int r = i >> 6, c2 = i & 63;
        const float* wr = w + (size_t)(n0 + r)*129 + c2*2;
        __half2 h = __floats2half2_rn(wr[0], wr[1]);
        *(unsigned*)&wsh[r*136 + c2*2] = *(unsigned*)&h;
    }
    if (tid < 64) bsh[tid] = w[(size_t)(n0 + tid)*129 + 128];
    __syncthreads();

    float acc[8][4];
#pragma unroll
    for (int nt = 0; nt < 8; nt++)
#pragma unroll
        for (int c = 0; c < 4; c++) acc[nt][c] = 0.f;

#pragma unroll
    for (int kk = 0; kk < 8; kk++) {
        unsigned af[4];
        const int ar = (warp*16 + g)*136 + kk*16 + tg*2;
        af[0] = *(const unsigned*)&xsh[ar];
        af[1] = *(const unsigned*)&xsh[ar + 8*136];
        af[2] = *(const unsigned*)&xsh[ar + 8];
        af[3] = *(const unsigned*)&xsh[ar + 8*136 + 8];
#pragma unroll
        for (int nt = 0; nt < 8; nt++) {
            const int br = (nt*8 + g)*136 + kk*16 + tg*2;
            unsigned bf[2];
            bf[0] = *(const unsigned*)&wsh[br];
            bf[1] = *(const unsigned*)&wsh[br + 8];
            mma16816_(acc[nt], af, bf);
        }
    }

#pragma unroll
    for (int nt = 0; nt < 8; nt++) {
        const int col = nt*8 + tg*2;
        acc[nt][0] += bsh[col];     acc[nt][1] += bsh[col + 1];
        acc[nt][2] += bsh[col];     acc[nt][3] += bsh[col + 1];
    }

    const int bi = m0 >> 9, tb = m0 & 511;
    const int cbase = n0 & 255;
    const int hh = n0 >> 8;

    if (cbase < 128) {
        __half* qg_ = g_qh + ((size_t)(bi*HH + hh)*TT + tb)*DD + cbase;
#pragma unroll
        for (int nt = 0; nt < 8; nt++) {
            const int col = nt*8 + tg*2;
            const int r0 = warp*16 + g;
            __half2 h01 = __floats2half2_rn(acc[nt][0], acc[nt][1]);
            __half2 h23 = __floats2half2_rn(acc[nt][2], acc[nt][3]);
            *(unsigned*)&qg_[(size_t)r0*DD + col]       = *(unsigned*)&h01;
            *(unsigned*)&qg_[(size_t)(r0 + 8)*DD + col] = *(unsigned*)&h23;
        }
    } else {
        __syncthreads();
        __half* vsm = xsh;   // 64 d-rows x 144
#pragma unroll
        for (int nt = 0; nt < 8; nt++) {
            const int dl = nt*8 + tg*2;
            const int r0 = warp*16 + g;
            vsm[dl*144 + r0]           = __float2half(acc[nt][0]);
            vsm[(dl + 1)*144 + r0]     = __float2half(acc[nt][1]);
            vsm[dl*144 + r0 + 8]       = __float2half(acc[nt][2]);
            vsm[(dl + 1)*144 + r0 + 8] = __float2half(acc[nt][3]);
        }
        __syncthreads();
        __half* vg = g_vT + ((size_t)(bi*HH + hh)*DD + (cbase - 128))*TT + tb;
        for (int i = tid; i < 64*16; i += 256) {
            int row = i >> 4, seg = i & 15;
            uint4 val = *(uint4*)&vsm[row*144 + seg*8];
            *(uint4*)&vg[(size_t)row*TT + seg*8] = val;
        }
    }
}

// ---------------------------------------------------------------------------
__global__ __launch_bounds__(256) void k_kernel(const float* __restrict__ x,
                                                const float* __restrict__ wk) {
    __shared__ float xs[16*128];
    __shared__ float wks[8*128];

    const int b = blockIdx.y, s0 = blockIdx.x * 16;
    const int tid = threadIdx.x;

    const float4* xg = (const float4*)(x + ((size_t)b*TT + s0)*DD);
    for (int i = tid; i < 16*32; i += 256) ((float4*)xs)[i] = xg[i];
    for (int i = tid; i < 8*32; i += 256)  ((float4*)wks)[i] = ((const float4*)wk)[i];
    __syncthreads();

    for (int i = tid; i < 16*8*32; i += 256) {
        int d4 = i & 31, hh = (i >> 5) & 7, sl = i >> 8;
        float4 xv = *(const float4*)&xs[sl*128 + d4*4];
        float4 wv = *(const float4*)&wks[hh*128 + d4*4];
        unsigned p = pack4i_(q1_(xv.x*wv.x), q1_(xv.y*wv.y),
                             q1_(xv.z*wv.z), q1_(xv.w*wv.w));
        *(unsigned*)&g_k8[((size_t)(b*HH + hh)*TT + s0 + sl)*DD + d4*4] = p;
    }
}

// ---------------------------------------------------------------------------
#define SSTRIDE 520
#define OFF_Q8 66560
#define OFF_K8 75776
#define OFF_VT 66560
#define ATTN_SMEM 101376

__global__ __launch_bounds__(256) void attn_kernel(const float* __restrict__ msk) {
    extern __shared__ char smc[];
    __half* Ssh = (__half*)smc;
    char*   q8  = smc + OFF_Q8;
    char*   k8  = smc + OFF_K8;

    const int b  = blockIdx.z, h = blockIdx.y;
    const int t0 = blockIdx.x * 64;
    const int tid = threadIdx.x;
    const int tx  = tid & 15, ty = tid >> 4;

    const uint4* khg8 = (const uint4*)(g_k8 + ((size_t)(b*HH + h))*TT*DD);

    const uint4* qg = (const uint4*)(g_qh + (((size_t)(b*HH + h))*TT + t0)*DD);
#pragma unroll
    for (int u = 0; u < 2; u++) {
        int idx = tid + u*256;
        int r = idx >> 3, seg = idx & 7;
        uint4 ha = qg[r*16 + seg*2];
        uint4 hb = qg[r*16 + seg*2 + 1];
        float2 f0 = __half22float2(*(__half2*)&ha.x);
        float2 f1 = __half22float2(*(__half2*)&ha.y);
        float2 f2 = __half22float2(*(__half2*)&ha.z);
        float2 f3 = __half22float2(*(__half2*)&ha.w);
        float2 f4 = __half22float2(*(__half2*)&hb.x);
        float2 f5 = __half22float2(*(__half2*)&hb.y);
        float2 f6 = __half22float2(*(__half2*)&hb.z);
        float2 f7 = __half22float2(*(__half2*)&hb.w);
        uint4 o;
        o.x = pack4i_(q1_(f0.x), q1_(f0.y), q1_(f1.x), q1_(f1.y));
        o.y = pack4i_(q1_(f2.x), q1_(f2.y), q1_(f3.x), q1_(f3.y));
        o.z = pack4i_(q1_(f4.x), q1_(f4.y), q1_(f5.x), q1_(f5.y));
        o.w = pack4i_(q1_(f6.x), q1_(f6.y), q1_(f7.x), q1_(f7.y));
        *(uint4*)&q8[r*144 + seg*16] = o;
    }

    uint4 kreg[2];
#pragma unroll
    for (int u = 0; u < 2; u++) kreg[u] = khg8[tid + u*256];

    for (int sc = 0; sc < 8; sc++) {
        const int s0 = sc * 64;
#pragma unroll
        for (int u = 0; u < 2; u++) {
            int idx = tid + u*256;
            int r = idx >> 3, seg = idx & 7;
            *(uint4*)&k8[r*144 + seg*16] = kreg[u];
        }
        __syncthreads();

        if (sc + 1 < 8) {
#pragma unroll
            for (int u = 0; u < 2; u++) kreg[u] = khg8[(sc + 1)*512 + tid + u*256];
        }

        unsigned acc[4][4];
#pragma unroll
        for (int i = 0; i < 4; i++)
#pragma unroll
            for (int j = 0; j < 4; j++) acc[i][j] = 0u;

#pragma unroll
        for (int ch = 0; ch < 8; ch++) {
            uint4 qv[4], kv[4];
#pragma unroll
            for (int i = 0; i < 4; i++) qv[i] = *(const uint4*)&q8[(ty*4 + i)*144 + ch*16];
#pragma unroll
            for (int j = 0; j < 4; j++) kv[j] = *(const uint4*)&k8[(tx + 16*j)*144 + ch*16];
#pragma unroll
            for (int i = 0; i < 4; i++)
#pragma unroll
                for (int j = 0; j < 4; j++) {
                    unsigned a = acc[i][j];
                    a = vad4_(qv[i].x, kv[j].x, a);
                    a = vad4_(qv[i].y, kv[j].y, a);
                    a = vad4_(qv[i].z, kv[j].z, a);
                    a = vad4_(qv[i].w, kv[j].w, a);
                    acc[i][j] = a;
                }
        }

#pragma unroll
        for (int i = 0; i < 4; i++)
#pragma unroll
            for (int j = 0; j < 4; j++)
                Ssh[(ty*4 + i)*SSTRIDE + s0 + tx + 16*j] =
                    __float2half((float)acc[i][j] * CNEG);
        __syncthreads();
    }

    // prefetch vT chunk 0 into registers (consumed in phase 3)
    const uint4* vTg4 = (const uint4*)(g_vT + ((size_t)(b*HH + h))*DD*TT);
    uint4 vreg[8];
#pragma unroll
    for (int u = 0; u < 8; u++) {
        int i = tid + u*256;
        int r = i >> 4, kg = i & 15;
        vreg[u] = vTg4[r*64 + kg];
    }

    // ---------------- Phase 2: row softmax + mask ----------------
    const int warp = tid >> 5, lane = tid & 31;
    for (int r = warp; r < 64; r += 8) {
        __half* row = Ssh + r*SSTRIDE;
        float vals[16];
        float m = -1e30f;
#pragma unroll
        for (int i = 0; i < 16; i++) {
            vals[i] = __half2float(row[lane + i*32]);
            m = fmaxf(m, vals[i]);
        }
#pragma unroll
        for (int o = 16; o > 0; o >>= 1) m = fmaxf(m, __shfl_xor_sync(0xffffffffu, m, o));
        float sum = 0.f;
#pragma unroll
        for (int i = 0; i < 16; i++) { vals[i] = __expf(vals[i] - m); sum += vals[i]; }
#pragma unroll
        for (int o = 16; o > 0; o >>= 1) sum += __shfl_xor_sync(0xffffffffu, sum, o);
        float inv = 1.f / sum;
        const float* mrow = msk + ((size_t)(h*TT + t0 + r))*TT;
#pragma unroll
        for (int i = 0; i < 16; i++)
            row[lane + i*32] = __float2half(vals[i] * inv * mrow[lane + i*32]);
    }
    __syncthreads();

    // ---------------- Phase 3: O = P @ V (vT double-buffered via regs) -----
    __half* vTsh = (__half*)(smc + OFF_VT);
    const int mt = warp & 3, ng = warp >> 2;
    const int g = lane >> 2, tg = lane & 3;

    float oacc[8][4];
#pragma unroll
    for (int nt = 0; nt < 8; nt++)
#pragma unroll
        for (int c = 0; c < 4; c++) oacc[nt][c] = 0.f;

    for (int sc = 0; sc < 4; sc++) {
#pragma unroll
        for (int u = 0; u < 8; u++) {
            int i = tid + u*256;
            int r = i >> 4, kg = i & 15;
            *(uint4*)&vTsh[r*136 + kg*8] = vreg[u];
        }
        __syncthreads();

        if (sc + 1 < 4) {
#pragma unroll
            for (int u = 0; u < 8; u++) {
                int i = tid + u*256;
                int r = i >> 4, kg = i & 15;
                vreg[u] = vTg4[r*64 + (sc + 1)*16 + kg];
            }
        }

#pragma unroll
        for (int kk = 0; kk < 8; kk++) {
            const int ar = (mt*16 + g)*SSTRIDE + sc*128 + kk*16 + tg*2;
            unsigned af[4];
            af[0] = *(const unsigned*)&Ssh[ar];
            af[1] = *(const unsigned*)&Ssh[ar + 8*SSTRIDE];
            af[2] = *(const unsigned*)&Ssh[ar + 8];
            af[3] = *(const unsigned*)&Ssh[ar + 8*SSTRIDE + 8];

            const int kb = kk*16 + tg*2;
#pragma unroll
            for (int nt = 0; nt < 8; nt++) {
                int row = ng*64 + nt*8 + g;
                unsigned bf[2];
                bf[0] = *(const unsigned*)&vTsh[row*136 + kb];
                bf[1] = *(const unsigned*)&vTsh[row*136 + kb + 8];
                mma16816_(oacc[nt], af, bf);
            }
        }
        __syncthreads();
    }

    __half* og = g_oh + (((size_t)(b*HH + h))*TT + t0)*DD;
#pragma unroll
    for (int nt = 0; nt < 8; nt++) {
        int d = ng*64 + nt*8 + tg*2;
        int r0 = mt*16 + g;
        __half2 h01 = __floats2half2_rn(oacc[nt][0], oacc[nt][1]);
        __half2 h23 = __floats2half2_rn(oacc[nt][2], oacc[nt][3]);
        *(unsigned*)&og[(size_t)r0*DD + d]       = *(unsigned*)&h01;
        *(unsigned*)&og[(size_t)(r0 + 8)*DD + d] = *(unsigned*)&h23;
    }
}

// ---------------------------------------------------------------------------
// Kernel 3: split into 512 CTAs (16 t-rows x 64 o-cols each)
// ---------------------------------------------------------------------------
#define FIN_SMEM (64*136*2 + 16*136*2 + 256)

__global__ __launch_bounds__(256) void final_kernel(const float* __restrict__ x,
                                                    const float* __restrict__ fw,
                                                    float* __restrict__ out) {
    extern __shared__ char fsm[];
    __half* Wh   = (__half*)fsm;                      // 64 x 136
    __half* yosh = (__half*)(fsm + 64*136*2);         // 16 x 136
    float*  bsh  = (float*)(fsm + 64*136*2 + 16*136*2);

    const int b = blockIdx.y;
    const int t0 = (blockIdx.x >> 1) * 16;
    const int o0 = (blockIdx.x & 1) * 64;
    const int tid = threadIdx.x;
    const int warp = tid >> 5, lane = tid & 31;
    const int g = lane >> 2, tg = lane & 3;

    for (int i = tid; i < 64*64; i += 256) {
        int r = i >> 6, c2 = i & 63;
        const float* wr = fw + (size_t)(o0 + r)*129 + c2*2;
        __half2 h = __floats2half2_rn(wr[0], wr[1]);
        *(unsigned*)&Wh[r*136 + c2*2] = *(unsigned*)&h;
    }
    if (tid < 64) bsh[tid] = fw[(size_t)(o0 + tid)*129 + 128];

    for (int i = tid; i < 16*64; i += 256) {
        int r = i >> 6, d2 = i & 63;
        float2 bo = make_float2(0.f, 0.f);
#pragma unroll
        for (int h = 0; h < HH; h++) {
            __half2 v = *(const __half2*)&g_oh[(((size_t)(b*HH + h))*TT + t0 + r)*DD + d2*2];
            float2 f = __half22float2(v);
            bo.x += f.x; bo.y += f.y;
        }
        float z0 = bo.x + 4.5f, z1 = bo.y + 4.5f;
        float s0 = 1.f / (1.f + __expf(-1.702f * z0));
        float s1 = 1.f / (1.f + __expf(-1.702f * z1));
        __half2 hy = __floats2half2_rn(z0*s0 - 4.5f, z1*s1 - 4.5f);
        *(unsigned*)&yosh[r*136 + d2*2] = *(unsigned*)&hy;
    }
    __syncthreads();

    float acc[4];
#pragma unroll
    for (int c = 0; c < 4; c++) acc[c] = 0.f;

#pragma unroll
    for (int kk = 0; kk < 8; kk++) {
        unsigned af[4];
        const int ar = g*136 + kk*16 + tg*2;
        af[0] = *(const unsigned*)&yosh[ar];
        af[1] = *(const unsigned*)&yosh[ar + 8*136];
        af[2] = *(const unsigned*)&yosh[ar + 8];
        af[3] = *(const unsigned*)&yosh[ar + 8*136 + 8];
        const int br = (warp*8 + g)*136 + kk*16 + tg*2;
        unsigned bf[2];
        bf[0] = *(const unsigned*)&Wh[br];
        bf[1] = *(const unsigned*)&Wh[br + 8];
        mma16816_(acc, af, bf);
    }

    {
        const int lcol = warp*8 + tg*2;
        const int col = o0 + lcol;
        const float b0 = bsh[lcol], b1 = bsh[lcol + 1];
        size_t i0 = ((size_t)b*TT + t0 + g)*DD + col;
        size_t i1 = ((size_t)b*TT + t0 + g + 8)*DD + col;
        out[i0]     = x[i0]     + acc[0] + b0;
        out[i0 + 1] = x[i0 + 1] + acc[1] + b1;
        out[i1]     = x[i1]     + acc[2] + b0;
        out[i1 + 1] = x[i1 + 1] + acc[3] + b1;
    }
}

// ---------------------------------------------------------------------------
extern "C" void kernel_launch(void* const* d_in, const int* in_sizes, int n_in,
                              void* d_out, int out_size) {
    const float* x   = (const float*)d_in[0];
    const float* msk = (const float*)d_in[1];
    const float* wqv = (const float*)d_in[2];
    const float* wk  = (const float*)d_in[3];
    const float* fw  = (const float*)d_in[4];
    float* out = (float*)d_out;

    cudaFuncSetAttribute(qv_kernel,    cudaFuncAttributeMaxDynamicSharedMemorySize,
                         QV_SMEM);
    cudaFuncSetAttribute(attn_kernel,  cudaFuncAttributeMaxDynamicSharedMemorySize,
                         ATTN_SMEM);
    cudaFuncSetAttribute(final_kernel, cudaFuncAttributeMaxDynamicSharedMemorySize,
                         FIN_SMEM);

    qv_kernel<<<dim3(32, 32), 256, QV_SMEM>>>(x, wqv);
    k_kernel<<<dim3(TT/16, BB), 256>>>(x, wk);
    attn_kernel<<<dim3(TT/64, HH, BB), 256, ATTN_SMEM>>>(msk);
    final_kernel<<<dim3(TT/16*2, BB), 256, FIN_SMEM>>>(x, fw, out);
}

// round 17
// speedup vs baseline: 2.4777x; 1.0340x over previous
#include <cuda_runtime.h>
#include <cuda_fp16.h>
#include <math.h>
#include <cstdint>

#define BB 8
#define TT 512
#define DD 128
#define HH 8

#define QINV  80.0f
#define CNEG  (-0.0011048543f)

typedef unsigned long long u64;

__device__ __forceinline__ void mma16816_(float* c, const unsigned* a, const unsigned* b) {
    asm volatile(
        "mma.sync.aligned.m16n8k16.row.col.f32.f16.f16.f32 "
        "{%0,%1,%2,%3}, {%4,%5,%6,%7}, {%8,%9}, {%0,%1,%2,%3};"
        : "+f"(c[0]), "+f"(c[1]), "+f"(c[2]), "+f"(c[3])
        : "r"(a[0]), "r"(a[1]), "r"(a[2]), "r"(a[3]), "r"(b[0]), "r"(b[1]));
}

__device__ __forceinline__ unsigned vad4_(unsigned a, unsigned b, unsigned c) {
    unsigned d;
    asm("vabsdiff4.u32.s32.s32.add %0, %1, %2, %3;" : "=r"(d) : "r"(a), "r"(b), "r"(c));
    return d;
}

__device__ __forceinline__ int q1_(float f) {
    int i = __float2int_rn(f * QINV);
    return max(-127, min(127, i));
}
__device__ __forceinline__ unsigned pack4i_(int a, int b, int c, int d) {
    return (unsigned)(a & 255) | ((unsigned)(b & 255) << 8) |
           ((unsigned)(c & 255) << 16) | ((unsigned)(d & 255) << 24);
}

__device__ __half g_qh[(size_t)BB*HH*TT*DD];
__device__ __align__(16) signed char g_k8[(size_t)BB*HH*TT*DD];
__device__ __half g_vT[(size_t)BB*HH*DD*TT];
__device__ __half g_oh[(size_t)BB*HH*TT*DD];

// ---------------------------------------------------------------------------
// Kernel 1: QV projection via mma.sync (128m x 64n tiles) + fused k8 epilogue.
// Each CTA also quantizes k8 for bt-rows [m0 + (n0/64)*4, +4), all 8 heads —
// the 32 n-tile CTAs of one m-block exactly cover its 128 rows.
// ---------------------------------------------------------------------------
#define QV_SMEM (128*136*2 + 64*136*2)

__global__ __launch_bounds__(256) void qv_kernel(const float* __restrict__ x,
                                                 const float* __restrict__ w,
                                                 const float* __restrict__ wk) {
    extern __shared__ __half smh[];
    __half* xsh = smh;             // 128 x 136
    __half* wsh = smh + 128*136;   // 64 x 136
    __shared__ float bsh[64];
    __shared__ float wks[8*128];

    const int tid = threadIdx.x;
    const int warp = tid >> 5, lane = tid & 31;
    const int g = lane >> 2, tg = lane & 3;
    const int m0 = blockIdx.y * 128;
    const int n0 = blockIdx.x * 64;

    // stage wk (for k8 epilogue)
    for (int i = tid; i < 8*32; i += 256)
        ((float4*)wks)[i] = ((const float4*)wk)[i];

    const float4* xg = (const float4*)(x + (size_t)m0*DD);
    for (int i = tid; i < 128*32; i += 256) {
        int r = i >> 5, c4 = i & 31;
        float4 v = xg[i];
        __half2 h0 = __floats2half2_rn(v.x, v.y);
        __half2 h1 = __floats2half2_rn(v.z, v.w);
        uint2 st; st.x = *(unsigned*)&h0; st.y = *(unsigned*)&h1;
        *(uint2*)&xsh[r*136 + c4*4] = st;
    }
    for (int i = tid; i < 64*64; i += 256) {
        int r = i >> 6, c2 = i & 63;
        const float* wr = w + (size_t)(n0 + r)*129 + c2*2;
        __half2 h = __floats2half2_rn(wr[0], wr[1]);
        *(unsigned*)&wsh[r*136 + c2*2] = *(unsigned*)&h;
    }
    if (tid < 64) bsh[tid] = w[(size_t)(n0 + tid)*129 + 128];
    __syncthreads();

    float acc[8][4];
#pragma unroll
    for (int nt = 0; nt < 8; nt++)
#pragma unroll
        for (int c = 0; c < 4; c++) acc[nt][c] = 0.f;

#pragma unroll
    for (int kk = 0; kk < 8; kk++) {
        unsigned af[4];
        const int ar = (warp*16 + g)*136 + kk*16 + tg*2;
        af[0] = *(const unsigned*)&xsh[ar];
        af[1] = *(const unsigned*)&xsh[ar + 8*136];
        af[2] = *(const unsigned*)&xsh[ar + 8];
        af[3] = *(const unsigned*)&xsh[ar + 8*136 + 8];
#pragma unroll
        for (int nt = 0; nt < 8; nt++) {
            const int br = (nt*8 + g)*136 + kk*16 + tg*2;
            unsigned bf[2];
            bf[0] = *(const unsigned*)&wsh[br];
            bf[1] = *(const unsigned*)&wsh[br + 8];
            mma16816_(acc[nt], af, bf);
        }
    }

#pragma unroll
    for (int nt = 0; nt < 8; nt++) {
        const int col = nt*8 + tg*2;
        acc[nt][0] += bsh[col];     acc[nt][1] += bsh[col + 1];
        acc[nt][2] += bsh[col];     acc[nt][3] += bsh[col + 1];
    }

    // ---- fused k8 epilogue: 4 bt-rows x 8 heads x 128 d (int8) ----
    {
        const int slice = n0 >> 6;            // 0..31
        const int r0k = m0 + slice*4;         // global bt row base
        for (int i = tid; i < 1024; i += 256) {
            int d4 = i & 31, hh2 = (i >> 5) & 7, sl = i >> 8;
            int bt = r0k + sl;
            int bi2 = bt >> 9, t2 = bt & 511;
            float4 xv = *(const float4*)&x[(size_t)bt*DD + d4*4];
            float4 wv = *(const float4*)&wks[hh2*128 + d4*4];
            unsigned p = pack4i_(q1_(xv.x*wv.x), q1_(xv.y*wv.y),
                                 q1_(xv.z*wv.z), q1_(xv.w*wv.w));
            *(unsigned*)&g_k8[((size_t)(bi2*HH + hh2)*TT + t2)*DD + d4*4] = p;
        }
    }

    const int bi = m0 >> 9, tb = m0 & 511;
    const int cbase = n0 & 255;
    const int hh = n0 >> 8;

    if (cbase < 128) {
        __half* qg_ = g_qh + ((size_t)(bi*HH + hh)*TT + tb)*DD + cbase;
#pragma unroll
        for (int nt = 0; nt < 8; nt++) {
            const int col = nt*8 + tg*2;
            const int r0 = warp*16 + g;
            __half2 h01 = __floats2half2_rn(acc[nt][0], acc[nt][1]);
            __half2 h23 = __floats2half2_rn(acc[nt][2], acc[nt][3]);
            *(unsigned*)&qg_[(size_t)r0*DD + col]       = *(unsigned*)&h01;
            *(unsigned*)&qg_[(size_t)(r0 + 8)*DD + col] = *(unsigned*)&h23;
        }
    } else {
        __syncthreads();
        __half* vsm = xsh;   // 64 d-rows x 144
#pragma unroll
        for (int nt = 0; nt < 8; nt++) {
            const int dl = nt*8 + tg*2;
            const int r0 = warp*16 + g;
            vsm[dl*144 + r0]           = __float2half(acc[nt][0]);
            vsm[(dl + 1)*144 + r0]     = __float2half(acc[nt][1]);
            vsm[dl*144 + r0 + 8]       = __float2half(acc[nt][2]);
            vsm[(dl + 1)*144 + r0 + 8] = __float2half(acc[nt][3]);
        }
        __syncthreads();
        __half* vg = g_vT + ((size_t)(bi*HH + hh)*DD + (cbase - 128))*TT + tb;
        for (int i = tid; i < 64*16; i += 256) {
            int row = i >> 4, seg = i & 15;
            uint4 val = *(uint4*)&vsm[row*144 + seg*8];
            *(uint4*)&vg[(size_t)row*TT + seg*8] = val;
        }
    }
}

// ---------------------------------------------------------------------------
// Kernel 2: fused L1 attention (int8 SAD + HMMA P@V; no-max softmax).
// ---------------------------------------------------------------------------
#define SSTRIDE 520
#define OFF_Q8 66560
#define OFF_K8 75776
#define OFF_VT 66560
#define ATTN_SMEM 101376

__global__ __launch_bounds__(256) void attn_kernel(const float* __restrict__ msk) {
    extern __shared__ char smc[];
    __half* Ssh = (__half*)smc;
    char*   q8  = smc + OFF_Q8;
    char*   k8  = smc + OFF_K8;

    const int b  = blockIdx.z, h = blockIdx.y;
    const int t0 = blockIdx.x * 64;
    const int tid = threadIdx.x;
    const int tx  = tid & 15, ty = tid >> 4;

    const uint4* khg8 = (const uint4*)(g_k8 + ((size_t)(b*HH + h))*TT*DD);

    const uint4* qg = (const uint4*)(g_qh + (((size_t)(b*HH + h))*TT + t0)*DD);
#pragma unroll
    for (int u = 0; u < 2; u++) {
        int idx = tid + u*256;
        int r = idx >> 3, seg = idx & 7;
        uint4 ha = qg[r*16 + seg*2];
        uint4 hb = qg[r*16 + seg*2 + 1];
        float2 f0 = __half22float2(*(__half2*)&ha.x);
        float2 f1 = __half22float2(*(__half2*)&ha.y);
        float2 f2 = __half22float2(*(__half2*)&ha.z);
        float2 f3 = __half22float2(*(__half2*)&ha.w);
        float2 f4 = __half22float2(*(__half2*)&hb.x);
        float2 f5 = __half22float2(*(__half2*)&hb.y);
        float2 f6 = __half22float2(*(__half2*)&hb.z);
        float2 f7 = __half22float2(*(__half2*)&hb.w);
        uint4 o;
        o.x = pack4i_(q1_(f0.x), q1_(f0.y), q1_(f1.x), q1_(f1.y));
        o.y = pack4i_(q1_(f2.x), q1_(f2.y), q1_(f3.x), q1_(f3.y));
        o.z = pack4i_(q1_(f4.x), q1_(f4.y), q1_(f5.x), q1_(f5.y));
        o.w = pack4i_(q1_(f6.x), q1_(f6.y), q1_(f7.x), q1_(f7.y));
        *(uint4*)&q8[r*144 + seg*16] = o;
    }

    uint4 kreg[2];
#pragma unroll
    for (int u = 0; u < 2; u++) kreg[u] = khg8[tid + u*256];

    for (int sc = 0; sc < 8; sc++) {
        const int s0 = sc * 64;
#pragma unroll
        for (int u = 0; u < 2; u++) {
            int idx = tid + u*256;
            int r = idx >> 3, seg = idx & 7;
            *(uint4*)&k8[r*144 + seg*16] = kreg[u];
        }
        __syncthreads();

        if (sc + 1 < 8) {
#pragma unroll
            for (int u = 0; u < 2; u++) kreg[u] = khg8[(sc + 1)*512 + tid + u*256];
        }

        unsigned acc[4][4];
#pragma unroll
        for (int i = 0; i < 4; i++)
#pragma unroll
            for (int j = 0; j < 4; j++) acc[i][j] = 0u;

#pragma unroll
        for (int ch = 0; ch < 8; ch++) {
            uint4 qv[4], kv[4];
#pragma unroll
            for (int i = 0; i < 4; i++) qv[i] = *(const uint4*)&q8[(ty*4 + i)*144 + ch*16];
#pragma unroll
            for (int j = 0; j < 4; j++) kv[j] = *(const uint4*)&k8[(tx + 16*j)*144 + ch*16];
#pragma unroll
            for (int i = 0; i < 4; i++)
#pragma unroll
                for (int j = 0; j < 4; j++) {
                    unsigned a = acc[i][j];
                    a = vad4_(qv[i].x, kv[j].x, a);
                    a = vad4_(qv[i].y, kv[j].y, a);
                    a = vad4_(qv[i].z, kv[j].z, a);
                    a = vad4_(qv[i].w, kv[j].w, a);
                    acc[i][j] = a;
                }
        }

#pragma unroll
        for (int i = 0; i < 4; i++)
#pragma unroll
            for (int j = 0; j < 4; j++)
                Ssh[(ty*4 + i)*SSTRIDE + s0 + tx + 16*j] =
                    __float2half((float)acc[i][j] * CNEG);
        __syncthreads();
    }

    // prefetch vT chunk 0 into registers (consumed in phase 3)
    const uint4* vTg4 = (const uint4*)(g_vT + ((size_t)(b*HH + h))*DD*TT);
    uint4 vreg[8];
#pragma unroll
    for (int u = 0; u < 8; u++) {
        int i = tid + u*256;
        int r = i >> 4, kg = i & 15;
        vreg[u] = vTg4[r*64 + kg];
    }

    // ---------------- Phase 2: softmax (no max pass: logits in [-36, 0]) ---
    const int warp = tid >> 5, lane = tid & 31;
    for (int r = warp; r < 64; r += 8) {
        __half* row = Ssh + r*SSTRIDE;
        float vals[16];
        float sum = 0.f;
#pragma unroll
        for (int i = 0; i < 16; i++) {
            vals[i] = __expf(__half2float(row[lane + i*32]));
            sum += vals[i];
        }
#pragma unroll
        for (int o = 16; o > 0; o >>= 1) sum += __shfl_xor_sync(0xffffffffu, sum, o);
        float inv = 1.f / sum;
        const float* mrow = msk + ((size_t)(h*TT + t0 + r))*TT;
#pragma unroll
        for (int i = 0; i < 16; i++)
            row[lane + i*32] = __float2half(vals[i] * inv * mrow[lane + i*32]);
    }
    __syncthreads();

    // ---------------- Phase 3: O = P @ V (vT double-buffered via regs) -----
    __half* vTsh = (__half*)(smc + OFF_VT);
    const int mt = warp & 3, ng = warp >> 2;
    const int g = lane >> 2, tg = lane & 3;

    float oacc[8][4];
#pragma unroll
    for (int nt = 0; nt < 8; nt++)
#pragma unroll
        for (int c = 0; c < 4; c++) oacc[nt][c] = 0.f;

    for (int sc = 0; sc < 4; sc++) {
#pragma unroll
        for (int u = 0; u < 8; u++) {
            int i = tid + u*256;
            int r = i >> 4, kg = i & 15;
            *(uint4*)&vTsh[r*136 + kg*8] = vreg[u];
        }
        __syncthreads();

        if (sc + 1 < 4) {
#pragma unroll
            for (int u = 0; u < 8; u++) {
                int i = tid + u*256;
                int r = i >> 4, kg = i & 15;
                vreg[u] = vTg4[r*64 + (sc + 1)*16 + kg];
            }
        }

#pragma unroll
        for (int kk = 0; kk < 8; kk++) {
            const int ar = (mt*16 + g)*SSTRIDE + sc*128 + kk*16 + tg*2;
            unsigned af[4];
            af[0] = *(const unsigned*)&Ssh[ar];
            af[1] = *(const unsigned*)&Ssh[ar + 8*SSTRIDE];
            af[2] = *(const unsigned*)&Ssh[ar + 8];
            af[3] = *(const unsigned*)&Ssh[ar + 8*SSTRIDE + 8];

            const int kb = kk*16 + tg*2;
#pragma unroll
            for (int nt = 0; nt < 8; nt++) {
                int row = ng*64 + nt*8 + g;
                unsigned bf[2];
                bf[0] = *(const unsigned*)&vTsh[row*136 + kb];
                bf[1] = *(const unsigned*)&vTsh[row*136 + kb + 8];
                mma16816_(oacc[nt], af, bf);
            }
        }
        __syncthreads();
    }

    __half* og = g_oh + (((size_t)(b*HH + h))*TT + t0)*DD;
#pragma unroll
    for (int nt = 0; nt < 8; nt++) {
        int d = ng*64 + nt*8 + tg*2;
        int r0 = mt*16 + g;
        __half2 h01 = __floats2half2_rn(oacc[nt][0], oacc[nt][1]);
        __half2 h23 = __floats2half2_rn(oacc[nt][2], oacc[nt][3]);
        *(unsigned*)&og[(size_t)r0*DD + d]       = *(unsigned*)&h01;
        *(unsigned*)&og[(size_t)(r0 + 8)*DD + d] = *(unsigned*)&h23;
    }
}

// ---------------------------------------------------------------------------
// Kernel 3: head-reduce + quickGELU + fanout HMMA + residual (512 CTAs).
// Reduce LDGs issued before W staging to overlap latencies.
// ---------------------------------------------------------------------------
#define FIN_SMEM (64*136*2 + 16*136*2 + 256)

__global__ __launch_bounds__(256) void final_kernel(const float* __restrict__ x,
                                                    const float* __restrict__ fw,
                                                    float* __restrict__ out) {
    extern __shared__ char fsm[];
    __half* Wh   = (__half*)fsm;                      // 64 x 136
    __half* yosh = (__half*)(fsm + 64*136*2);         // 16 x 136
    float*  bsh  = (float*)(fsm + 64*136*2 + 16*136*2);

    const int b = blockIdx.y;
    const int t0 = (blockIdx.x >> 1) * 16;
    const int o0 = (blockIdx.x & 1) * 64;
    const int tid = threadIdx.x;
    const int warp = tid >> 5, lane = tid & 31;
    const int g = lane >> 2, tg = lane & 3;

    // h-reduce first (issues the long-latency g_oh loads early)
    {
        int i = tid;                       // 16*64 = 1024 -> 4 iters of 256
#pragma unroll
        for (int it = 0; it < 4; it++, i += 256) {
            int r = i >> 6, d2 = i & 63;
            float2 bo = make_float2(0.f, 0.f);
#pragma unroll
            for (int h = 0; h < HH; h++) {
                __half2 v = *(const __half2*)&g_oh[(((size_t)(b*HH + h))*TT + t0 + r)*DD + d2*2];
                float2 f = __half22float2(v);
                bo.x += f.x; bo.y += f.y;
            }
            float z0 = bo.x + 4.5f, z1 = bo.y + 4.5f;
            float s0 = 1.f / (1.f + __expf(-1.702f * z0));
            float s1 = 1.f / (1.f + __expf(-1.702f * z1));
            __half2 hy = __floats2half2_rn(z0*s0 - 4.5f, z1*s1 - 4.5f);
            *(unsigned*)&yosh[r*136 + d2*2] = *(unsigned*)&hy;
        }
    }

    for (int i = tid; i < 64*64; i += 256) {
        int r = i >> 6, c2 = i & 63;
        const float* wr = fw + (size_t)(o0 + r)*129 + c2*2;
        __half2 h = __floats2half2_rn(wr[0], wr[1]);
        *(unsigned*)&Wh[r*136 + c2*2] = *(unsigned*)&h;
    }
    if (tid < 64) bsh[tid] = fw[(size_t)(o0 + tid)*129 + 128];
    __syncthreads();

    float acc[4];
#pragma unroll
    for (int c = 0; c < 4; c++) acc[c] = 0.f;

#pragma unroll
    for (int kk = 0; kk < 8; kk++) {
        unsigned af[4];
        const int ar = g*136 + kk*16 + tg*2;
        af[0] = *(const unsigned*)&yosh[ar];
        af[1] = *(const unsigned*)&yosh[ar + 8*136];
        af[2] = *(const unsigned*)&yosh[ar + 8];
        af[3] = *(const unsigned*)&yosh[ar + 8*136 + 8];
        const int br = (warp*8 + g)*136 + kk*16 + tg*2;
        unsigned bf[2];
        bf[0] = *(const unsigned*)&Wh[br];
        bf[1] = *(const unsigned*)&Wh[br + 8];
        mma16816_(acc, af, bf);
    }

    {
        const int lcol = warp*8 + tg*2;
        const int col = o0 + lcol;
        const float b0 = bsh[lcol], b1 = bsh[lcol + 1];
        size_t i0 = ((size_t)b*TT + t0 + g)*DD + col;
        size_t i1 = ((size_t)b*TT + t0 + g + 8)*DD + col;
        out[i0]     = x[i0]     + acc[0] + b0;
        out[i0 + 1] = x[i0 + 1] + acc[1] + b1;
        out[i1]     = x[i1]     + acc[2] + b0;
        out[i1 + 1] = x[i1 + 1] + acc[3] + b1;
    }
}

// ---------------------------------------------------------------------------
extern "C" void kernel_launch(void* const* d_in, const int* in_sizes, int n_in,
                              void* d_out, int out_size) {
    const float* x   = (const float*)d_in[0];
    const float* msk = (const float*)d_in[1];
    const float* wqv = (const float*)d_in[2];
    const float* wk  = (const float*)d_in[3];
    const float* fw  = (const float*)d_in[4];
    float* out = (float*)d_out;

    cudaFuncSetAttribute(qv_kernel,    cudaFuncAttributeMaxDynamicSharedMemorySize,
                         QV_SMEM);
    cudaFuncSetAttribute(attn_kernel,  cudaFuncAttributeMaxDynamicSharedMemorySize,
                         ATTN_SMEM);
    cudaFuncSetAttribute(final_kernel, cudaFuncAttributeMaxDynamicSharedMemorySize,
                         FIN_SMEM);

    qv_kernel<<<dim3(32, 32), 256, QV_SMEM>>>(x, wqv, wk);
    attn_kernel<<<dim3(TT/64, HH, BB), 256, ATTN_SMEM>>>(msk);
    final_kernel<<<dim3(TT/16*2, BB), 256, FIN_SMEM>>>(x, fw, out);
}